// round 1
// baseline (speedup 1.0000x reference)
#include <cuda_runtime.h>
#include <math.h>

// ---------------- problem constants ----------------
#define BATCH 8
#define TT 1024
#define HH 1024
#define NHEAD 16
#define HD 64
#define MROWS (BATCH * TT)   // 8192

// ---------------- scratch (device globals; no allocs allowed) ----------------
__device__ float g_x[MROWS * HH];        // running residual stream
__device__ float g_ln[MROWS * HH];       // LN output
__device__ float g_h[MROWS * 2 * HH];    // FFN hidden / conv hidden
__device__ float g_qkv[MROWS * 3 * HH];  // qkv projection
__device__ float g_attn[MROWS * HH];     // attention output

// ---------------- helpers ----------------
__device__ __forceinline__ float gelu_exact(float x) { return x * normcdff(x); }

__device__ __forceinline__ unsigned f2tf32(float x) {
    unsigned r;
    asm("cvt.rna.tf32.f32 %0, %1;" : "=r"(r) : "f"(x));
    return r;
}

__device__ __forceinline__ void mma_tf32(float c[4], const unsigned a[4], const unsigned b[2]) {
    asm volatile(
        "mma.sync.aligned.m16n8k8.row.col.f32.tf32.tf32.f32 "
        "{%0,%1,%2,%3}, {%4,%5,%6,%7}, {%8,%9}, {%0,%1,%2,%3};"
        : "+f"(c[0]), "+f"(c[1]), "+f"(c[2]), "+f"(c[3])
        : "r"(a[0]), "r"(a[1]), "r"(a[2]), "r"(a[3]), "r"(b[0]), "r"(b[1]));
}

// ---------------- LayerNorm: one block per row of 1024 ----------------
__global__ void ln_kernel(const float* __restrict__ in, const float* __restrict__ gam,
                          const float* __restrict__ bet, float* __restrict__ out) {
    int row = blockIdx.x;
    int tid = threadIdx.x;  // 256
    const float4* p = (const float4*)(in + (size_t)row * HH);
    float4 v = p[tid];
    float s = v.x + v.y + v.z + v.w;
    float ss = v.x * v.x + v.y * v.y + v.z * v.z + v.w * v.w;
    #pragma unroll
    for (int o = 16; o > 0; o >>= 1) {
        s += __shfl_xor_sync(0xffffffffu, s, o);
        ss += __shfl_xor_sync(0xffffffffu, ss, o);
    }
    __shared__ float rs[8], rss[8];
    __shared__ float sh_mean, sh_rstd;
    if ((tid & 31) == 0) { rs[tid >> 5] = s; rss[tid >> 5] = ss; }
    __syncthreads();
    if (tid == 0) {
        float S = 0.f, SS = 0.f;
        #pragma unroll
        for (int i = 0; i < 8; i++) { S += rs[i]; SS += rss[i]; }
        float mean = S * (1.0f / HH);
        float var = SS * (1.0f / HH) - mean * mean;
        sh_mean = mean;
        sh_rstd = rsqrtf(var + 1e-5f);
    }
    __syncthreads();
    float mean = sh_mean, rstd = sh_rstd;
    float4 gv = ((const float4*)gam)[tid];
    float4 bv = ((const float4*)bet)[tid];
    float4 o4;
    o4.x = (v.x - mean) * rstd * gv.x + bv.x;
    o4.y = (v.y - mean) * rstd * gv.y + bv.y;
    o4.z = (v.z - mean) * rstd * gv.z + bv.z;
    o4.w = (v.w - mean) * rstd * gv.w + bv.w;
    ((float4*)(out + (size_t)row * HH))[tid] = o4;
}

// ---------------- generic TF32 tensor-core GEMM ----------------
// C[M,N] = epi(A[M,K] @ op(B) + bias[N], resid)
// BT=false: B is [K,N] row-major. BT=true: B is [N,K] row-major (i.e. B^T).
// EPI: 0=bias only, 1=gelu(acc+bias), 2=resid + (acc+bias), 3=resid + 0.5*(acc+bias)
#define EPI_BIAS 0
#define EPI_GELU 1
#define EPI_RES  2
#define EPI_RESH 3

#define BM 128
#define BN 128
#define BKK 32

template <bool BT, int EPI>
__global__ __launch_bounds__(256) void gemm_tf32(
    const float* __restrict__ A, const float* __restrict__ B,
    const float* __restrict__ bias, const float* __restrict__ resid,
    float* __restrict__ C, int M, int N, int Kd) {
    __shared__ float As[BKK][BM + 4];
    __shared__ float Bs[BKK][BN + 4];
    int tid = threadIdx.x;
    int warp = tid >> 5, lane = tid & 31;
    int wm = warp >> 1;  // 0..3 -> 32 rows each
    int wn = warp & 1;   // 0..1 -> 64 cols each
    int g = lane >> 2;   // 0..7
    int q = lane & 3;    // 0..3
    int bm0 = blockIdx.y * BM, bn0 = blockIdx.x * BN;

    float c[2][8][4];
    #pragma unroll
    for (int i = 0; i < 2; i++)
        #pragma unroll
        for (int j = 0; j < 8; j++)
            #pragma unroll
            for (int t = 0; t < 4; t++) c[i][j][t] = 0.f;

    for (int k0 = 0; k0 < Kd; k0 += BKK) {
        // A tile -> As[k][m] (transposed store)
        {
            int kc = (tid & 7) * 4;
            int r0 = tid >> 3;
            #pragma unroll
            for (int i = 0; i < 4; i++) {
                int m = r0 + i * 32;
                float4 v = *(const float4*)&A[(size_t)(bm0 + m) * Kd + k0 + kc];
                As[kc + 0][m] = v.x; As[kc + 1][m] = v.y;
                As[kc + 2][m] = v.z; As[kc + 3][m] = v.w;
            }
        }
        if (!BT) {
            int nc = (tid & 31) * 4;
            int kr = tid >> 5;
            #pragma unroll
            for (int i = 0; i < 4; i++) {
                int kk = kr + i * 8;
                float4 v = *(const float4*)&B[(size_t)(k0 + kk) * N + bn0 + nc];
                *(float4*)&Bs[kk][nc] = v;
            }
        } else {
            int kc = (tid & 7) * 4;
            int n0 = tid >> 3;
            #pragma unroll
            for (int i = 0; i < 4; i++) {
                int n = n0 + i * 32;
                float4 v = *(const float4*)&B[(size_t)(bn0 + n) * Kd + k0 + kc];
                Bs[kc + 0][n] = v.x; Bs[kc + 1][n] = v.y;
                Bs[kc + 2][n] = v.z; Bs[kc + 3][n] = v.w;
            }
        }
        __syncthreads();
        #pragma unroll
        for (int ks = 0; ks < BKK; ks += 8) {
            unsigned afr[2][4], bfr[8][2];
            #pragma unroll
            for (int mt = 0; mt < 2; mt++) {
                int mr = wm * 32 + mt * 16 + g;
                afr[mt][0] = f2tf32(As[ks + q][mr]);
                afr[mt][1] = f2tf32(As[ks + q][mr + 8]);
                afr[mt][2] = f2tf32(As[ks + q + 4][mr]);
                afr[mt][3] = f2tf32(As[ks + q + 4][mr + 8]);
            }
            #pragma unroll
            for (int nt = 0; nt < 8; nt++) {
                int nc = wn * 64 + nt * 8 + g;
                bfr[nt][0] = f2tf32(Bs[ks + q][nc]);
                bfr[nt][1] = f2tf32(Bs[ks + q + 4][nc]);
            }
            #pragma unroll
            for (int mt = 0; mt < 2; mt++)
                #pragma unroll
                for (int nt = 0; nt < 8; nt++) mma_tf32(c[mt][nt], afr[mt], bfr[nt]);
        }
        __syncthreads();
    }

    // epilogue
    #pragma unroll
    for (int mt = 0; mt < 2; mt++) {
        #pragma unroll
        for (int nt = 0; nt < 8; nt++) {
            int r0 = bm0 + wm * 32 + mt * 16 + g;
            int cc = bn0 + wn * 64 + nt * 8 + 2 * q;
            float b0 = bias[cc], b1 = bias[cc + 1];
            #pragma unroll
            for (int half = 0; half < 2; half++) {
                int r = r0 + half * 8;
                size_t o0 = (size_t)r * N + cc;
                float v0 = c[mt][nt][half * 2 + 0] + b0;
                float v1 = c[mt][nt][half * 2 + 1] + b1;
                if (EPI == EPI_GELU) {
                    v0 = gelu_exact(v0); v1 = gelu_exact(v1);
                } else if (EPI == EPI_RES) {
                    v0 += resid[o0]; v1 += resid[o0 + 1];
                } else if (EPI == EPI_RESH) {
                    v0 = resid[o0] + 0.5f * v0; v1 = resid[o0 + 1] + 0.5f * v1;
                }
                C[o0] = v0; C[o0 + 1] = v1;
            }
        }
    }
}

// ---------------- flash attention (causal, fp32 SIMT) ----------------
// grid: (T/64, B*NH), 256 threads (16x16), dynamic smem: 4 * 64*68 floats
__global__ __launch_bounds__(256) void attn_kernel(const float* __restrict__ qkv,
                                                   float* __restrict__ out) {
    extern __shared__ float smx[];
    float (*Qs)[68] = (float (*)[68])smx;
    float (*Ks)[68] = (float (*)[68])(smx + 64 * 68);
    float (*Vs)[68] = (float (*)[68])(smx + 2 * 64 * 68);
    float (*Ps)[68] = (float (*)[68])(smx + 3 * 64 * 68);

    int bh = blockIdx.y;
    int b = bh >> 4, h = bh & 15;
    int qt = blockIdx.x;
    int tid = threadIdx.x;
    int tx = tid & 15, ty = tid >> 4;
    int ty4 = ty * 4, tx4 = tx * 4;
    const float scale = 0.125f;  // 1/sqrt(64)
    size_t base = (size_t)b * TT * 3072 + (size_t)h * 64;

    // load Q tile (scaled)
    for (int it = tid; it < 64 * 16; it += 256) {
        int r = it >> 4, c4 = (it & 15) * 4;
        float4 v = *(const float4*)&qkv[base + (size_t)(qt * 64 + r) * 3072 + c4];
        Qs[r][c4 + 0] = v.x * scale; Qs[r][c4 + 1] = v.y * scale;
        Qs[r][c4 + 2] = v.z * scale; Qs[r][c4 + 3] = v.w * scale;
    }

    float m_i[4], l_i[4], acc[4][4];
    #pragma unroll
    for (int i = 0; i < 4; i++) {
        m_i[i] = -1e30f; l_i[i] = 0.f;
        #pragma unroll
        for (int j = 0; j < 4; j++) acc[i][j] = 0.f;
    }

    for (int kt = 0; kt <= qt; kt++) {
        __syncthreads();  // protect Ks/Vs/Ps from previous iteration readers
        for (int it = tid; it < 2 * 64 * 16; it += 256) {
            int which = it >> 10;  // 0 = K, 1 = V
            int r = (it & 1023) >> 4, c4 = (it & 15) * 4;
            float4 v = *(const float4*)&qkv[base + (size_t)(kt * 64 + r) * 3072 +
                                            1024 + which * 1024 + c4];
            float (*dst)[68] = which ? Vs : Ks;
            dst[r][c4 + 0] = v.x; dst[r][c4 + 1] = v.y;
            dst[r][c4 + 2] = v.z; dst[r][c4 + 3] = v.w;
        }
        __syncthreads();

        // S = Q @ K^T for this thread's 4x4 tile
        float s[4][4];
        #pragma unroll
        for (int i = 0; i < 4; i++)
            #pragma unroll
            for (int j = 0; j < 4; j++) s[i][j] = 0.f;
        #pragma unroll 4
        for (int kk = 0; kk < 64; kk += 4) {
            float4 a[4], bb[4];
            #pragma unroll
            for (int i = 0; i < 4; i++) a[i] = *(const float4*)&Qs[ty4 + i][kk];
            #pragma unroll
            for (int j = 0; j < 4; j++) bb[j] = *(const float4*)&Ks[tx4 + j][kk];
            #pragma unroll
            for (int i = 0; i < 4; i++)
                #pragma unroll
                for (int j = 0; j < 4; j++)
                    s[i][j] += a[i].x * bb[j].x + a[i].y * bb[j].y +
                               a[i].z * bb[j].z + a[i].w * bb[j].w;
        }
        if (kt == qt) {
            #pragma unroll
            for (int i = 0; i < 4; i++)
                #pragma unroll
                for (int j = 0; j < 4; j++)
                    if (tx4 + j > ty4 + i) s[i][j] = -1e30f;
        }

        // online softmax update (per-row stats replicated across the 16 tx lanes)
        #pragma unroll
        for (int i = 0; i < 4; i++) {
            float mx = fmaxf(fmaxf(s[i][0], s[i][1]), fmaxf(s[i][2], s[i][3]));
            #pragma unroll
            for (int o = 8; o > 0; o >>= 1) mx = fmaxf(mx, __shfl_xor_sync(0xffffffffu, mx, o));
            float m_new = fmaxf(m_i[i], mx);
            float corr = __expf(m_i[i] - m_new);
            l_i[i] *= corr;
            #pragma unroll
            for (int j = 0; j < 4; j++) acc[i][j] *= corr;
            float psum = 0.f;
            #pragma unroll
            for (int j = 0; j < 4; j++) {
                float p = __expf(s[i][j] - m_new);
                psum += p;
                Ps[ty4 + i][tx4 + j] = p;
            }
            #pragma unroll
            for (int o = 8; o > 0; o >>= 1) psum += __shfl_xor_sync(0xffffffffu, psum, o);
            l_i[i] += psum;
            m_i[i] = m_new;
        }
        __syncthreads();

        // acc += P @ V
        #pragma unroll 4
        for (int kk = 0; kk < 64; kk += 4) {
            float4 p4[4];
            #pragma unroll
            for (int i = 0; i < 4; i++) p4[i] = *(const float4*)&Ps[ty4 + i][kk];
            #pragma unroll
            for (int t = 0; t < 4; t++) {
                float4 vv = *(const float4*)&Vs[kk + t][tx4];
                #pragma unroll
                for (int i = 0; i < 4; i++) {
                    float pv = (t == 0) ? p4[i].x : (t == 1) ? p4[i].y : (t == 2) ? p4[i].z : p4[i].w;
                    acc[i][0] += pv * vv.x; acc[i][1] += pv * vv.y;
                    acc[i][2] += pv * vv.z; acc[i][3] += pv * vv.w;
                }
            }
        }
    }

    #pragma unroll
    for (int i = 0; i < 4; i++) {
        float inv = 1.0f / l_i[i];
        int row = b * TT + qt * 64 + ty4 + i;
        size_t o0 = (size_t)row * HH + h * 64 + tx4;
        float4 o4;
        o4.x = acc[i][0] * inv; o4.y = acc[i][1] * inv;
        o4.z = acc[i][2] * inv; o4.w = acc[i][3] * inv;
        *(float4*)&out[o0] = o4;
    }
}

// ---------------- depthwise conv (K=3, causal left pad) + gelu ----------------
__global__ void dwconv_gelu_kernel(const float* __restrict__ ln, const float* __restrict__ dwk,
                                   const float* __restrict__ dwb, float* __restrict__ out) {
    int i = blockIdx.x * blockDim.x + threadIdx.x;  // over MROWS*HH
    int ch = i & (HH - 1);
    int row = i >> 10;
    int t = row & (TT - 1);
    int b = row >> 10;
    float accv = dwb[ch];
    #pragma unroll
    for (int j = 0; j < 3; j++) {
        int tt = t - 2 + j;
        if (tt >= 0)
            accv += ln[((size_t)(b * TT + tt)) * HH + ch] * dwk[ch * 3 + j];
    }
    out[i] = gelu_exact(accv);
}

// ---------------- driver ----------------
extern "C" void kernel_launch(void* const* d_in, const int* in_sizes, int n_in,
                              void* d_out, int out_size) {
    const float* x       = (const float*)d_in[0];
    const float* ln1_g   = (const float*)d_in[1];
    const float* ln1_b   = (const float*)d_in[2];
    const float* ffn1_w1 = (const float*)d_in[3];
    const float* ffn1_b1 = (const float*)d_in[4];
    const float* ffn1_w2 = (const float*)d_in[5];
    const float* ffn1_b2 = (const float*)d_in[6];
    const float* an_g    = (const float*)d_in[7];
    const float* an_b    = (const float*)d_in[8];
    const float* qkv_w   = (const float*)d_in[9];
    const float* qkv_b   = (const float*)d_in[10];
    const float* out_w   = (const float*)d_in[11];
    const float* out_b   = (const float*)d_in[12];
    const float* cn_g    = (const float*)d_in[13];
    const float* cn_b    = (const float*)d_in[14];
    const float* dw_k    = (const float*)d_in[15];
    const float* dw_b    = (const float*)d_in[16];
    const float* pw_w    = (const float*)d_in[17];
    const float* pw_b    = (const float*)d_in[18];
    const float* ln2_g   = (const float*)d_in[19];
    const float* ln2_b   = (const float*)d_in[20];
    const float* ffn2_w1 = (const float*)d_in[21];
    const float* ffn2_b1 = (const float*)d_in[22];
    const float* ffn2_w2 = (const float*)d_in[23];
    const float* ffn2_b2 = (const float*)d_in[24];
    float* outp = (float*)d_out;

    float *p_x, *p_ln, *p_h, *p_qkv, *p_attn;
    cudaGetSymbolAddress((void**)&p_x, g_x);
    cudaGetSymbolAddress((void**)&p_ln, g_ln);
    cudaGetSymbolAddress((void**)&p_h, g_h);
    cudaGetSymbolAddress((void**)&p_qkv, g_qkv);
    cudaGetSymbolAddress((void**)&p_attn, g_attn);

    int attn_smem = 4 * 64 * 68 * sizeof(float);
    cudaFuncSetAttribute(attn_kernel, cudaFuncAttributeMaxDynamicSharedMemorySize, attn_smem);

    dim3 blk(256);
    dim3 gN1024(1024 / BN, MROWS / BM);
    dim3 gN2048(2048 / BN, MROWS / BM);
    dim3 gN3072(3072 / BN, MROWS / BM);

    // 1) x = x + 0.5*FFN1(x)
    ln_kernel<<<MROWS, 256>>>(x, ln1_g, ln1_b, p_ln);
    gemm_tf32<false, EPI_GELU><<<gN2048, blk>>>(p_ln, ffn1_w1, ffn1_b1, nullptr, p_h, MROWS, 2048, 1024);
    gemm_tf32<false, EPI_RESH><<<gN1024, blk>>>(p_h, ffn1_w2, ffn1_b2, x, p_x, MROWS, 1024, 2048);

    // 2) attention
    ln_kernel<<<MROWS, 256>>>(p_x, an_g, an_b, p_ln);
    gemm_tf32<false, EPI_BIAS><<<gN3072, blk>>>(p_ln, qkv_w, qkv_b, nullptr, p_qkv, MROWS, 3072, 1024);
    attn_kernel<<<dim3(TT / 64, BATCH * NHEAD), 256, attn_smem>>>(p_qkv, p_attn);
    gemm_tf32<false, EPI_RES><<<gN1024, blk>>>(p_attn, out_w, out_b, p_x, p_x, MROWS, 1024, 1024);

    // 3) conv module
    ln_kernel<<<MROWS, 256>>>(p_x, cn_g, cn_b, p_ln);
    dwconv_gelu_kernel<<<(MROWS * HH) / 256, 256>>>(p_ln, dw_k, dw_b, p_h);
    gemm_tf32<true, EPI_RES><<<gN1024, blk>>>(p_h, pw_w, pw_b, p_x, p_x, MROWS, 1024, 1024);

    // 4) x = x + 0.5*FFN2(x)
    ln_kernel<<<MROWS, 256>>>(p_x, ln2_g, ln2_b, p_ln);
    gemm_tf32<false, EPI_GELU><<<gN2048, blk>>>(p_ln, ffn2_w1, ffn2_b1, nullptr, p_h, MROWS, 2048, 1024);
    gemm_tf32<false, EPI_RESH><<<gN1024, blk>>>(p_h, ffn2_w2, ffn2_b2, p_x, outp, MROWS, 1024, 2048);
}

// round 4
// speedup vs baseline: 2.1277x; 2.1277x over previous
#include <cuda_runtime.h>
#include <math.h>

// ---------------- problem constants ----------------
#define BATCH 8
#define TT 1024
#define HH 1024
#define NHEAD 16
#define MROWS (BATCH * TT)   // 8192

// ---------------- scratch (device globals) ----------------
__device__ float g_x[MROWS * HH];
__device__ float g_ln[MROWS * HH];
__device__ float g_h[MROWS * 2 * HH];
__device__ float g_qkv[MROWS * 3 * HH];
__device__ float g_attn[MROWS * HH];
__device__ float g_w[13631488];   // tf32-rounded weights, concatenated

// weight offsets in g_w
#define W_FFN1W1 0
#define W_FFN1W2 2097152
#define W_QKVW   4194304
#define W_OUTW   7340032
#define W_PWW    8388608
#define W_FFN2W1 9437184
#define W_FFN2W2 11534336

// ---------------- helpers ----------------
__device__ __forceinline__ float gelu_exact(float x) { return x * normcdff(x); }

__device__ __forceinline__ float tf32r(float x) {
    unsigned u;
    asm("cvt.rna.tf32.f32 %0, %1;" : "=r"(u) : "f"(x));
    return __uint_as_float(u);
}
__device__ __forceinline__ unsigned fbits(float x) { return __float_as_uint(x); }

__device__ __forceinline__ void mma_tf32(float c[4], const unsigned a[4], const unsigned b[2]) {
    asm volatile(
        "mma.sync.aligned.m16n8k8.row.col.f32.tf32.tf32.f32 "
        "{%0,%1,%2,%3}, {%4,%5,%6,%7}, {%8,%9}, {%0,%1,%2,%3};"
        : "+f"(c[0]), "+f"(c[1]), "+f"(c[2]), "+f"(c[3])
        : "r"(a[0]), "r"(a[1]), "r"(a[2]), "r"(a[3]), "r"(b[0]), "r"(b[1]));
}

__device__ __forceinline__ void cpasync16(unsigned s, const void* g) {
    asm volatile("cp.async.cg.shared.global [%0], [%1], 16;\n" :: "r"(s), "l"(g));
}
__device__ __forceinline__ void cpcommit() { asm volatile("cp.async.commit_group;\n"); }
template <int N>
__device__ __forceinline__ void cpwait() { asm volatile("cp.async.wait_group %0;\n" :: "n"(N)); }

// fast exp via FMA-pipe polynomial 2^f (avoids MUFU bottleneck)
#define LOG2E 1.4426950408889634f
__device__ __forceinline__ float exp2fast(float t) {
    t = fmaxf(t, -126.0f);
    float fi = floorf(t);
    float f = t - fi;
    float p = 1.5403530e-4f;
    p = fmaf(p, f, 1.3333558e-3f);
    p = fmaf(p, f, 9.6180399e-3f);
    p = fmaf(p, f, 5.5504109e-2f);
    p = fmaf(p, f, 2.4022651e-1f);
    p = fmaf(p, f, 6.9314718e-1f);
    p = fmaf(p, f, 1.0f);
    float sc = __int_as_float(((int)fi + 127) << 23);
    return p * sc;
}

// ---------------- weight tf32 rounding pass ----------------
__global__ void cvtw_kernel(const float4* __restrict__ in, float4* __restrict__ out, int n4) {
    int i = blockIdx.x * blockDim.x + threadIdx.x;
    if (i < n4) {
        float4 v = in[i];
        v.x = tf32r(v.x); v.y = tf32r(v.y); v.z = tf32r(v.z); v.w = tf32r(v.w);
        out[i] = v;
    }
}

// ---------------- LayerNorm (tf32-rounded output: feeds GEMMs) ----------------
__global__ void ln_kernel(const float* __restrict__ in, const float* __restrict__ gam,
                          const float* __restrict__ bet, float* __restrict__ out) {
    int row = blockIdx.x;
    int tid = threadIdx.x;  // 256
    const float4* p = (const float4*)(in + (size_t)row * HH);
    float4 v = p[tid];
    float s = v.x + v.y + v.z + v.w;
    float ss = v.x * v.x + v.y * v.y + v.z * v.z + v.w * v.w;
    #pragma unroll
    for (int o = 16; o > 0; o >>= 1) {
        s += __shfl_xor_sync(0xffffffffu, s, o);
        ss += __shfl_xor_sync(0xffffffffu, ss, o);
    }
    __shared__ float rs[8], rss[8];
    __shared__ float sh_mean, sh_rstd;
    if ((tid & 31) == 0) { rs[tid >> 5] = s; rss[tid >> 5] = ss; }
    __syncthreads();
    if (tid == 0) {
        float S = 0.f, SS = 0.f;
        #pragma unroll
        for (int i = 0; i < 8; i++) { S += rs[i]; SS += rss[i]; }
        float mean = S * (1.0f / HH);
        float var = SS * (1.0f / HH) - mean * mean;
        sh_mean = mean;
        sh_rstd = rsqrtf(var + 1e-5f);
    }
    __syncthreads();
    float mean = sh_mean, rstd = sh_rstd;
    float4 gv = ((const float4*)gam)[tid];
    float4 bv = ((const float4*)bet)[tid];
    float4 o4;
    o4.x = tf32r((v.x - mean) * rstd * gv.x + bv.x);
    o4.y = tf32r((v.y - mean) * rstd * gv.y + bv.y);
    o4.z = tf32r((v.z - mean) * rstd * gv.z + bv.z);
    o4.w = tf32r((v.w - mean) * rstd * gv.w + bv.w);
    ((float4*)(out + (size_t)row * HH))[tid] = o4;
}

// ---------------- pipelined TF32 GEMM ----------------
#define EPI_BIAS 0
#define EPI_GELU 1
#define EPI_RES  2
#define EPI_RESH 3

template <bool BT, int EPI>
__global__ __launch_bounds__(256) void gemm2(
    const float* __restrict__ A, const float* __restrict__ B,
    const float* __restrict__ bias, const float* __restrict__ resid,
    float* __restrict__ C, int M, int N, int Kd) {
    constexpr int ASTR = 36;
    constexpr int BSTR = BT ? 36 : 136;
    constexpr int ASZ = 128 * 36;
    constexpr int BSZ = BT ? 128 * 36 : 32 * 136;
    extern __shared__ float sm[];
    float* As = sm;
    float* Bs = sm + 2 * ASZ;
    unsigned asb = (unsigned)__cvta_generic_to_shared(As);
    unsigned bsb = (unsigned)__cvta_generic_to_shared(Bs);

    int tid = threadIdx.x, warp = tid >> 5, lane = tid & 31;
    int wm = warp >> 1, wn = warp & 1, g = lane >> 2, q = lane & 3;
    int bm0 = blockIdx.y * 128, bn0 = blockIdx.x * 128;

    float c[2][8][4];
    #pragma unroll
    for (int i = 0; i < 2; i++)
        #pragma unroll
        for (int j = 0; j < 8; j++)
            #pragma unroll
            for (int t = 0; t < 4; t++) c[i][j][t] = 0.f;

    const int nk = Kd >> 5;

    auto load_stage = [&](int k0, int st) {
        #pragma unroll
        for (int i = 0; i < 4; i++) {
            int cc = tid + 256 * i;
            int m = cc >> 3, j = cc & 7;
            cpasync16(asb + (unsigned)(st * ASZ + m * ASTR + j * 4) * 4u,
                      &A[(size_t)(bm0 + m) * Kd + k0 + j * 4]);
        }
        if (!BT) {
            #pragma unroll
            for (int i = 0; i < 4; i++) {
                int cc = tid + 256 * i;
                int kk = cc >> 5, j = cc & 31;
                cpasync16(bsb + (unsigned)(st * BSZ + kk * BSTR + j * 4) * 4u,
                          &B[(size_t)(k0 + kk) * N + bn0 + j * 4]);
            }
        } else {
            #pragma unroll
            for (int i = 0; i < 4; i++) {
                int cc = tid + 256 * i;
                int n = cc >> 3, j = cc & 7;
                cpasync16(bsb + (unsigned)(st * BSZ + n * BSTR + j * 4) * 4u,
                          &B[(size_t)(bn0 + n) * Kd + k0 + j * 4]);
            }
        }
        cpcommit();
    };

    load_stage(0, 0);
    for (int it = 0; it < nk; it++) {
        if (it + 1 < nk) { load_stage((it + 1) << 5, (it + 1) & 1); cpwait<1>(); }
        else cpwait<0>();
        __syncthreads();
        const float* Ac = As + (it & 1) * ASZ;
        const float* Bc = Bs + (it & 1) * BSZ;
        #pragma unroll
        for (int ks = 0; ks < 32; ks += 8) {
            unsigned a[2][4], b[8][2];
            #pragma unroll
            for (int mt = 0; mt < 2; mt++) {
                int mr = wm * 32 + mt * 16 + g;
                a[mt][0] = fbits(Ac[mr * ASTR + ks + q]);
                a[mt][1] = fbits(Ac[(mr + 8) * ASTR + ks + q]);
                a[mt][2] = fbits(Ac[mr * ASTR + ks + q + 4]);
                a[mt][3] = fbits(Ac[(mr + 8) * ASTR + ks + q + 4]);
            }
            #pragma unroll
            for (int nt = 0; nt < 8; nt++) {
                int nc = wn * 64 + nt * 8 + g;
                if (!BT) {
                    b[nt][0] = fbits(Bc[(ks + q) * BSTR + nc]);
                    b[nt][1] = fbits(Bc[(ks + q + 4) * BSTR + nc]);
                } else {
                    b[nt][0] = fbits(Bc[nc * BSTR + ks + q]);
                    b[nt][1] = fbits(Bc[nc * BSTR + ks + q + 4]);
                }
            }
            #pragma unroll
            for (int mt = 0; mt < 2; mt++)
                #pragma unroll
                for (int nt = 0; nt < 8; nt++) mma_tf32(c[mt][nt], a[mt], b[nt]);
        }
        __syncthreads();
    }

    // epilogue
    #pragma unroll
    for (int mt = 0; mt < 2; mt++) {
        #pragma unroll
        for (int nt = 0; nt < 8; nt++) {
            int r0 = bm0 + wm * 32 + mt * 16 + g;
            int cc = bn0 + wn * 64 + nt * 8 + 2 * q;
            float b0 = bias[cc], b1 = bias[cc + 1];
            #pragma unroll
            for (int half = 0; half < 2; half++) {
                int r = r0 + half * 8;
                size_t o0 = (size_t)r * N + cc;
                float v0 = c[mt][nt][half * 2 + 0] + b0;
                float v1 = c[mt][nt][half * 2 + 1] + b1;
                if (EPI == EPI_BIAS) {
                    v0 = tf32r(v0); v1 = tf32r(v1);
                } else if (EPI == EPI_GELU) {
                    v0 = tf32r(gelu_exact(v0)); v1 = tf32r(gelu_exact(v1));
                } else if (EPI == EPI_RES) {
                    v0 += resid[o0]; v1 += resid[o0 + 1];
                } else if (EPI == EPI_RESH) {
                    v0 = resid[o0] + 0.5f * v0; v1 = resid[o0 + 1] + 0.5f * v1;
                }
                C[o0] = v0; C[o0 + 1] = v1;
            }
        }
    }
}

// ---------------- flash attention with tf32 mma ----------------
// grid (T/128, B*NH), 256 threads (8 warps x 16 q-rows).
// smem: QP[128*68] (Q, then reused for P), KsT[64*64] (swizzled K^T), Vs[64*72]
__global__ __launch_bounds__(256) void attn2(const float* __restrict__ qkv,
                                             float* __restrict__ out) {
    extern __shared__ float sm[];
    float* QP  = sm;                 // 128*68
    float* KsT = sm + 128 * 68;      // 64*64 (xor-swizzled columns)
    float* Vs  = KsT + 64 * 64;      // 64*72

    int bh = blockIdx.y;
    int b = bh >> 4, h = bh & 15;
    int qb = blockIdx.x;
    int tid = threadIdx.x, warp = tid >> 5, lane = tid & 31;
    int g = lane >> 2, q = lane & 3;
    int wrow = warp * 16;
    size_t base = (size_t)b * TT * 3072 + (size_t)h * 64;

    // load Q strip (scaled by 1/8)
    #pragma unroll
    for (int i = 0; i < 8; i++) {
        int cc = tid + 256 * i;
        int r = cc >> 4, c4 = (cc & 15) * 4;
        float4 v = *(const float4*)&qkv[base + (size_t)(qb * 128 + r) * 3072 + c4];
        QP[r * 68 + c4 + 0] = v.x * 0.125f;
        QP[r * 68 + c4 + 1] = v.y * 0.125f;
        QP[r * 68 + c4 + 2] = v.z * 0.125f;
        QP[r * 68 + c4 + 3] = v.w * 0.125f;
    }
    __syncthreads();

    // Q fragments -> registers
    unsigned qa[8][4];
    #pragma unroll
    for (int s = 0; s < 8; s++) {
        qa[s][0] = fbits(QP[(wrow + g) * 68 + s * 8 + q]);
        qa[s][1] = fbits(QP[(wrow + g + 8) * 68 + s * 8 + q]);
        qa[s][2] = fbits(QP[(wrow + g) * 68 + s * 8 + q + 4]);
        qa[s][3] = fbits(QP[(wrow + g + 8) * 68 + s * 8 + q + 4]);
    }
    __syncthreads();  // all warps done reading Q -> QP reusable as P

    float m0 = -1e30f, m1 = -1e30f, l0 = 0.f, l1 = 0.f;
    float o[8][4];
    #pragma unroll
    for (int nt = 0; nt < 8; nt++)
        #pragma unroll
        for (int t = 0; t < 4; t++) o[nt][t] = 0.f;

    int ktmax = 2 * qb + 1;
    for (int kt = 0; kt <= ktmax; kt++) {
        __syncthreads();  // protect KsT/Vs reuse
        // K tile: transposed + swizzled store. V tile: natural.
        #pragma unroll
        for (int i = 0; i < 4; i++) {
            int cc = tid + 256 * i;
            int r = cc >> 4, t = cc & 15, c4 = t * 4;
            float4 v = *(const float4*)&qkv[base + (size_t)(kt * 64 + r) * 3072 + 1024 + c4];
            int sw = t << 1;  // ((d>>2)<<1), d>>2 == t for all 4 components
            KsT[(c4 + 0) * 64 + ((r ^ 0)  ^ sw)] = v.x;
            KsT[(c4 + 1) * 64 + ((r ^ 8)  ^ sw)] = v.y;
            KsT[(c4 + 2) * 64 + ((r ^ 16) ^ sw)] = v.z;
            KsT[(c4 + 3) * 64 + ((r ^ 24) ^ sw)] = v.w;
        }
        #pragma unroll
        for (int i = 0; i < 4; i++) {
            int cc = tid + 256 * i;
            int r = cc >> 4, c4 = (cc & 15) * 4;
            float4 v = *(const float4*)&qkv[base + (size_t)(kt * 64 + r) * 3072 + 2048 + c4];
            *(float4*)&Vs[r * 72 + c4] = v;
        }
        __syncthreads();

        bool active = (kt * 64) <= (qb * 128 + wrow + 15);
        if (active) {
            // S = Q @ K^T
            float s4[8][4];
            #pragma unroll
            for (int nt = 0; nt < 8; nt++)
                #pragma unroll
                for (int t = 0; t < 4; t++) s4[nt][t] = 0.f;
            #pragma unroll
            for (int s = 0; s < 8; s++) {
                int d0 = s * 8 + q, d1 = s * 8 + q + 4;
                int sw0 = ((d0 & 3) << 3) ^ ((d0 >> 2) << 1);
                int sw1 = ((d1 & 3) << 3) ^ ((d1 >> 2) << 1);
                unsigned kb[8][2];
                #pragma unroll
                for (int nt = 0; nt < 8; nt++) {
                    kb[nt][0] = fbits(KsT[d0 * 64 + ((nt * 8 + g) ^ sw0)]);
                    kb[nt][1] = fbits(KsT[d1 * 64 + ((nt * 8 + g) ^ sw1)]);
                }
                #pragma unroll
                for (int nt = 0; nt < 8; nt++) mma_tf32(s4[nt], qa[s], kb[nt]);
            }
            // causal mask
            if (kt * 64 + 63 > qb * 128 + wrow) {
                int r0 = qb * 128 + wrow + g, r1 = r0 + 8;
                #pragma unroll
                for (int nt = 0; nt < 8; nt++) {
                    int c0 = kt * 64 + nt * 8 + 2 * q;
                    if (c0 > r0)     s4[nt][0] = -1e30f;
                    if (c0 + 1 > r0) s4[nt][1] = -1e30f;
                    if (c0 > r1)     s4[nt][2] = -1e30f;
                    if (c0 + 1 > r1) s4[nt][3] = -1e30f;
                }
            }
            // online softmax (row halves g, g+8); stats over the 4 q-lanes
            float mx0 = -1e30f, mx1 = -1e30f;
            #pragma unroll
            for (int nt = 0; nt < 8; nt++) {
                mx0 = fmaxf(mx0, fmaxf(s4[nt][0], s4[nt][1]));
                mx1 = fmaxf(mx1, fmaxf(s4[nt][2], s4[nt][3]));
            }
            mx0 = fmaxf(mx0, __shfl_xor_sync(0xffffffffu, mx0, 1));
            mx0 = fmaxf(mx0, __shfl_xor_sync(0xffffffffu, mx0, 2));
            mx1 = fmaxf(mx1, __shfl_xor_sync(0xffffffffu, mx1, 1));
            mx1 = fmaxf(mx1, __shfl_xor_sync(0xffffffffu, mx1, 2));
            float mn0 = fmaxf(m0, mx0), mn1 = fmaxf(m1, mx1);
            float cr0 = exp2fast((m0 - mn0) * LOG2E);
            float cr1 = exp2fast((m1 - mn1) * LOG2E);
            float rs0 = 0.f, rs1 = 0.f;
            #pragma unroll
            for (int nt = 0; nt < 8; nt++) {
                float p0 = exp2fast((s4[nt][0] - mn0) * LOG2E);
                float p1 = exp2fast((s4[nt][1] - mn0) * LOG2E);
                float p2 = exp2fast((s4[nt][2] - mn1) * LOG2E);
                float p3 = exp2fast((s4[nt][3] - mn1) * LOG2E);
                rs0 += p0 + p1; rs1 += p2 + p3;
                float2 v01 = make_float2(tf32r(p0), tf32r(p1));
                *(float2*)&QP[(wrow + g) * 68 + nt * 8 + 2 * q] = v01;
                float2 v23 = make_float2(tf32r(p2), tf32r(p3));
                *(float2*)&QP[(wrow + g + 8) * 68 + nt * 8 + 2 * q] = v23;
            }
            rs0 += __shfl_xor_sync(0xffffffffu, rs0, 1);
            rs0 += __shfl_xor_sync(0xffffffffu, rs0, 2);
            rs1 += __shfl_xor_sync(0xffffffffu, rs1, 1);
            rs1 += __shfl_xor_sync(0xffffffffu, rs1, 2);
            l0 = l0 * cr0 + rs0; l1 = l1 * cr1 + rs1;
            #pragma unroll
            for (int nt = 0; nt < 8; nt++) {
                o[nt][0] *= cr0; o[nt][1] *= cr0;
                o[nt][2] *= cr1; o[nt][3] *= cr1;
            }
            m0 = mn0; m1 = mn1;
            __syncwarp();

            // O += P @ V
            #pragma unroll
            for (int s = 0; s < 8; s++) {
                unsigned pa[4];
                pa[0] = fbits(QP[(wrow + g) * 68 + s * 8 + q]);
                pa[1] = fbits(QP[(wrow + g + 8) * 68 + s * 8 + q]);
                pa[2] = fbits(QP[(wrow + g) * 68 + s * 8 + q + 4]);
                pa[3] = fbits(QP[(wrow + g + 8) * 68 + s * 8 + q + 4]);
                unsigned vb[8][2];
                #pragma unroll
                for (int nt = 0; nt < 8; nt++) {
                    vb[nt][0] = fbits(Vs[(s * 8 + q) * 72 + nt * 8 + g]);
                    vb[nt][1] = fbits(Vs[(s * 8 + q + 4) * 72 + nt * 8 + g]);
                }
                #pragma unroll
                for (int nt = 0; nt < 8; nt++) mma_tf32(o[nt], pa, vb[nt]);
            }
        }
    }

    // epilogue: normalize, round (feeds out-proj GEMM), store
    float i0 = 1.0f / l0, i1 = 1.0f / l1;
    int r0 = b * TT + qb * 128 + wrow + g;
    #pragma unroll
    for (int nt = 0; nt < 8; nt++) {
        int col = h * 64 + nt * 8 + 2 * q;
        float2 v0 = make_float2(tf32r(o[nt][0] * i0), tf32r(o[nt][1] * i0));
        *(float2*)&out[(size_t)r0 * HH + col] = v0;
        float2 v1 = make_float2(tf32r(o[nt][2] * i1), tf32r(o[nt][3] * i1));
        *(float2*)&out[(size_t)(r0 + 8) * HH + col] = v1;
    }
}

// ---------------- depthwise conv (K=3, causal) + gelu (tf32-rounded out) ----------------
__global__ void dwconv_gelu_kernel(const float* __restrict__ ln, const float* __restrict__ dwk,
                                   const float* __restrict__ dwb, float* __restrict__ out) {
    int i = blockIdx.x * blockDim.x + threadIdx.x;
    int ch = i & (HH - 1);
    int row = i >> 10;
    int t = row & (TT - 1);
    int b = row >> 10;
    float accv = dwb[ch];
    #pragma unroll
    for (int j = 0; j < 3; j++) {
        int tt = t - 2 + j;
        if (tt >= 0)
            accv += ln[((size_t)(b * TT + tt)) * HH + ch] * dwk[ch * 3 + j];
    }
    out[i] = tf32r(gelu_exact(accv));
}

// ---------------- driver ----------------
extern "C" void kernel_launch(void* const* d_in, const int* in_sizes, int n_in,
                              void* d_out, int out_size) {
    const float* x       = (const float*)d_in[0];
    const float* ln1_g   = (const float*)d_in[1];
    const float* ln1_b   = (const float*)d_in[2];
    const float* ffn1_w1 = (const float*)d_in[3];
    const float* ffn1_b1 = (const float*)d_in[4];
    const float* ffn1_w2 = (const float*)d_in[5];
    const float* ffn1_b2 = (const float*)d_in[6];
    const float* an_g    = (const float*)d_in[7];
    const float* an_b    = (const float*)d_in[8];
    const float* qkv_w   = (const float*)d_in[9];
    const float* qkv_b   = (const float*)d_in[10];
    const float* out_w   = (const float*)d_in[11];
    const float* out_b   = (const float*)d_in[12];
    const float* cn_g    = (const float*)d_in[13];
    const float* cn_b    = (const float*)d_in[14];
    const float* dw_k    = (const float*)d_in[15];
    const float* dw_b    = (const float*)d_in[16];
    const float* pw_w    = (const float*)d_in[17];
    const float* pw_b    = (const float*)d_in[18];
    const float* ln2_g   = (const float*)d_in[19];
    const float* ln2_b   = (const float*)d_in[20];
    const float* ffn2_w1 = (const float*)d_in[21];
    const float* ffn2_b1 = (const float*)d_in[22];
    const float* ffn2_w2 = (const float*)d_in[23];
    const float* ffn2_b2 = (const float*)d_in[24];
    float* outp = (float*)d_out;

    float *p_x, *p_ln, *p_h, *p_qkv, *p_attn, *p_w;
    cudaGetSymbolAddress((void**)&p_x, g_x);
    cudaGetSymbolAddress((void**)&p_ln, g_ln);
    cudaGetSymbolAddress((void**)&p_h, g_h);
    cudaGetSymbolAddress((void**)&p_qkv, g_qkv);
    cudaGetSymbolAddress((void**)&p_attn, g_attn);
    cudaGetSymbolAddress((void**)&p_w, g_w);

    // dynamic smem attributes
    const int smA = (2 * 128 * 36 + 2 * 32 * 136) * 4;  // 71680 (BT=false)
    const int smB = (2 * 128 * 36 + 2 * 128 * 36) * 4;  // 73728 (BT=true)
    const int smAttn = (128 * 68 + 64 * 64 + 64 * 72) * 4;  // 69632
    cudaFuncSetAttribute(gemm2<false, EPI_GELU>, cudaFuncAttributeMaxDynamicSharedMemorySize, smA);
    cudaFuncSetAttribute(gemm2<false, EPI_RESH>, cudaFuncAttributeMaxDynamicSharedMemorySize, smA);
    cudaFuncSetAttribute(gemm2<false, EPI_BIAS>, cudaFuncAttributeMaxDynamicSharedMemorySize, smA);
    cudaFuncSetAttribute(gemm2<false, EPI_RES>,  cudaFuncAttributeMaxDynamicSharedMemorySize, smA);
    cudaFuncSetAttribute(gemm2<true, EPI_RES>,   cudaFuncAttributeMaxDynamicSharedMemorySize, smB);
    cudaFuncSetAttribute(attn2, cudaFuncAttributeMaxDynamicSharedMemorySize, smAttn);

    // weight rounding pass (tf32 RNA)
    auto cvt = [&](const float* src, float* dst, int n) {
        cvtw_kernel<<<(n / 4 + 255) / 256, 256>>>((const float4*)src, (float4*)dst, n / 4);
    };
    cvt(ffn1_w1, p_w + W_FFN1W1, 2097152);
    cvt(ffn1_w2, p_w + W_FFN1W2, 2097152);
    cvt(qkv_w,   p_w + W_QKVW,   3145728);
    cvt(out_w,   p_w + W_OUTW,   1048576);
    cvt(pw_w,    p_w + W_PWW,    1048576);
    cvt(ffn2_w1, p_w + W_FFN2W1, 2097152);
    cvt(ffn2_w2, p_w + W_FFN2W2, 2097152);

    dim3 blk(256);
    dim3 gN1024(1024 / 128, MROWS / 128);
    dim3 gN2048(2048 / 128, MROWS / 128);
    dim3 gN3072(3072 / 128, MROWS / 128);

    // 1) x = x + 0.5*FFN1(x)
    ln_kernel<<<MROWS, 256>>>(x, ln1_g, ln1_b, p_ln);
    gemm2<false, EPI_GELU><<<gN2048, blk, smA>>>(p_ln, p_w + W_FFN1W1, ffn1_b1, nullptr, p_h, MROWS, 2048, 1024);
    gemm2<false, EPI_RESH><<<gN1024, blk, smA>>>(p_h, p_w + W_FFN1W2, ffn1_b2, x, p_x, MROWS, 1024, 2048);

    // 2) attention
    ln_kernel<<<MROWS, 256>>>(p_x, an_g, an_b, p_ln);
    gemm2<false, EPI_BIAS><<<gN3072, blk, smA>>>(p_ln, p_w + W_QKVW, qkv_b, nullptr, p_qkv, MROWS, 3072, 1024);
    attn2<<<dim3(TT / 128, BATCH * NHEAD), 256, smAttn>>>(p_qkv, p_attn);
    gemm2<false, EPI_RES><<<gN1024, blk, smA>>>(p_attn, p_w + W_OUTW, out_b, p_x, p_x, MROWS, 1024, 1024);

    // 3) conv module
    ln_kernel<<<MROWS, 256>>>(p_x, cn_g, cn_b, p_ln);
    dwconv_gelu_kernel<<<(MROWS * HH) / 256, 256>>>(p_ln, dw_k, dw_b, p_h);
    gemm2<true, EPI_RES><<<gN1024, blk, smB>>>(p_h, p_w + W_PWW, pw_b, p_x, p_x, MROWS, 1024, 1024);

    // 4) x = x + 0.5*FFN2(x)
    ln_kernel<<<MROWS, 256>>>(p_x, ln2_g, ln2_b, p_ln);
    gemm2<false, EPI_GELU><<<gN2048, blk, smA>>>(p_ln, p_w + W_FFN2W1, ffn2_b1, nullptr, p_h, MROWS, 2048, 1024);
    gemm2<false, EPI_RESH><<<gN1024, blk, smA>>>(p_h, p_w + W_FFN2W2, ffn2_b2, p_x, outp, MROWS, 1024, 2048);
}

// round 6
// speedup vs baseline: 3.5226x; 1.6556x over previous
#include <cuda_runtime.h>
#include <cuda_fp16.h>
#include <math.h>
#include <stdint.h>

// ---------------- problem constants ----------------
#define BATCH 8
#define TT 1024
#define HH 1024
#define NHEAD 16
#define MROWS (BATCH * TT)   // 8192

// ---------------- scratch (device globals) ----------------
__device__ float  g_x[MROWS * HH];            // residual stream (fp32)
__device__ __half g_lnh[MROWS * HH];          // LN output (fp16)
__device__ __half g_hh[MROWS * 2 * HH];       // FFN hidden / conv hidden (fp16)
__device__ __half g_qkvh[MROWS * 3 * HH];     // qkv (fp16)
__device__ __half g_attnh[MROWS * HH];        // attention out (fp16)
__device__ __half g_wh[13631488];             // fp16 TRANSPOSED weights [N,K]

#define W_FFN1W1 0
#define W_FFN1W2 2097152
#define W_QKVW   4194304
#define W_OUTW   7340032
#define W_PWW    8388608
#define W_FFN2W1 9437184
#define W_FFN2W2 11534336

// ---------------- helpers ----------------
__device__ __forceinline__ float gelu_exact(float x) { return x * normcdff(x); }
__device__ __forceinline__ unsigned fbits(float x) { return __float_as_uint(x); }
__device__ __forceinline__ float tf32r(float x) {
    unsigned u;
    asm("cvt.rna.tf32.f32 %0, %1;" : "=r"(u) : "f"(x));
    return __uint_as_float(u);
}

__device__ __forceinline__ void mma_tf32(float c[4], const unsigned a[4], const unsigned b[2]) {
    asm volatile(
        "mma.sync.aligned.m16n8k8.row.col.f32.tf32.tf32.f32 "
        "{%0,%1,%2,%3}, {%4,%5,%6,%7}, {%8,%9}, {%0,%1,%2,%3};"
        : "+f"(c[0]), "+f"(c[1]), "+f"(c[2]), "+f"(c[3])
        : "r"(a[0]), "r"(a[1]), "r"(a[2]), "r"(a[3]), "r"(b[0]), "r"(b[1]));
}

__device__ __forceinline__ void mma_f16(float c[4], const unsigned a[4], const unsigned b[2]) {
    asm volatile(
        "mma.sync.aligned.m16n8k16.row.col.f32.f16.f16.f32 "
        "{%0,%1,%2,%3}, {%4,%5,%6,%7}, {%8,%9}, {%0,%1,%2,%3};"
        : "+f"(c[0]), "+f"(c[1]), "+f"(c[2]), "+f"(c[3])
        : "r"(a[0]), "r"(a[1]), "r"(a[2]), "r"(a[3]), "r"(b[0]), "r"(b[1]));
}

__device__ __forceinline__ void ldsm4(unsigned r[4], uint32_t a) {
    asm volatile("ldmatrix.sync.aligned.m8n8.x4.shared.b16 {%0,%1,%2,%3}, [%4];"
                 : "=r"(r[0]), "=r"(r[1]), "=r"(r[2]), "=r"(r[3]) : "r"(a));
}

__device__ __forceinline__ void cpasync16(unsigned s, const void* g) {
    asm volatile("cp.async.cg.shared.global [%0], [%1], 16;\n" :: "r"(s), "l"(g));
}
__device__ __forceinline__ void cpcommit() { asm volatile("cp.async.commit_group;\n"); }
template <int N>
__device__ __forceinline__ void cpwait() { asm volatile("cp.async.wait_group %0;\n" :: "n"(N)); }

#define LOG2E 1.4426950408889634f
__device__ __forceinline__ float exp2fast(float t) {
    t = fmaxf(t, -126.0f);
    float fi = floorf(t);
    float f = t - fi;
    float p = 1.5403530e-4f;
    p = fmaf(p, f, 1.3333558e-3f);
    p = fmaf(p, f, 9.6180399e-3f);
    p = fmaf(p, f, 5.5504109e-2f);
    p = fmaf(p, f, 2.4022651e-1f);
    p = fmaf(p, f, 6.9314718e-1f);
    p = fmaf(p, f, 1.0f);
    float sc = __int_as_float(((int)fi + 127) << 23);
    return p * sc;
}

// ---------------- weight fp16 convert (pw_w: already [N,K]) ----------------
__global__ void cvtw_kernel(const float4* __restrict__ in, __half* __restrict__ out, int n4) {
    int i = blockIdx.x * blockDim.x + threadIdx.x;
    if (i < n4) {
        float4 v = in[i];
        __half2* o = (__half2*)(out + i * 4);
        o[0] = __floats2half2_rn(v.x, v.y);
        o[1] = __floats2half2_rn(v.z, v.w);
    }
}

// ---------------- weight fp16 convert + transpose: in[R,C] -> out[C,R] ----------------
__global__ void cvtT_kernel(const float* __restrict__ in, __half* __restrict__ out,
                            int R, int C) {
    __shared__ float t[32][33];
    int r0 = blockIdx.x * 32, c0 = blockIdx.y * 32;
    int tx = threadIdx.x, ty = threadIdx.y;  // 32 x 8
    #pragma unroll
    for (int i = 0; i < 4; i++)
        t[ty + i * 8][tx] = in[(size_t)(r0 + ty + i * 8) * C + c0 + tx];
    __syncthreads();
    #pragma unroll
    for (int i = 0; i < 4; i++)
        out[(size_t)(c0 + ty + i * 8) * R + r0 + tx] = __float2half_rn(t[tx][ty + i * 8]);
}

// ---------------- LayerNorm: fp32 in -> fp16 out ----------------
__global__ void ln_kernel(const float* __restrict__ in, const float* __restrict__ gam,
                          const float* __restrict__ bet, __half* __restrict__ out) {
    int row = blockIdx.x;
    int tid = threadIdx.x;  // 256
    const float4* p = (const float4*)(in + (size_t)row * HH);
    float4 v = p[tid];
    float s = v.x + v.y + v.z + v.w;
    float ss = v.x * v.x + v.y * v.y + v.z * v.z + v.w * v.w;
    #pragma unroll
    for (int o = 16; o > 0; o >>= 1) {
        s += __shfl_xor_sync(0xffffffffu, s, o);
        ss += __shfl_xor_sync(0xffffffffu, ss, o);
    }
    __shared__ float rs[8], rss[8];
    __shared__ float sh_mean, sh_rstd;
    if ((tid & 31) == 0) { rs[tid >> 5] = s; rss[tid >> 5] = ss; }
    __syncthreads();
    if (tid == 0) {
        float S = 0.f, SS = 0.f;
        #pragma unroll
        for (int i = 0; i < 8; i++) { S += rs[i]; SS += rss[i]; }
        float mean = S * (1.0f / HH);
        float var = SS * (1.0f / HH) - mean * mean;
        sh_mean = mean;
        sh_rstd = rsqrtf(var + 1e-5f);
    }
    __syncthreads();
    float mean = sh_mean, rstd = sh_rstd;
    float4 gv = ((const float4*)gam)[tid];
    float4 bv = ((const float4*)bet)[tid];
    __half2* o = (__half2*)(out + (size_t)row * HH + tid * 4);
    o[0] = __floats2half2_rn((v.x - mean) * rstd * gv.x + bv.x,
                             (v.y - mean) * rstd * gv.y + bv.y);
    o[1] = __floats2half2_rn((v.z - mean) * rstd * gv.z + bv.z,
                             (v.w - mean) * rstd * gv.w + bv.w);
}

// ---------------- FP16 tensor-core GEMM: C[M,N] = epi(A[M,K] @ Bt[N,K]^T) ----------------
// 128x128 tile, BK=64, 2-stage cp.async, 256 threads, ldmatrix fragments.
#define EPI_BIAS 0
#define EPI_GELU 1
#define EPI_RES  2
#define EPI_RESH 3

#define HSTR 72              // halves per smem row (144 bytes)
#define TILE_B (128 * 144)   // bytes per tile stage

template <int EPI, bool OUTH>
__global__ __launch_bounds__(256) void gemm4(
    const __half* __restrict__ A, const __half* __restrict__ Bt,
    const float* __restrict__ bias, const float* __restrict__ resid,
    void* __restrict__ Cv, int N, int K) {
    extern __shared__ char smc[];
    uint32_t asb = (uint32_t)__cvta_generic_to_shared(smc);            // A: 2 stages
    uint32_t bsb = asb + 2 * TILE_B;                                   // B: 2 stages

    int tid = threadIdx.x, warp = tid >> 5, lane = tid & 31;
    int wm = warp >> 1, wn = warp & 1, g = lane >> 2, q = lane & 3;
    int bm0 = blockIdx.y * 128, bn0 = blockIdx.x * 128;

    float c[2][8][4];
    #pragma unroll
    for (int i = 0; i < 2; i++)
        #pragma unroll
        for (int j = 0; j < 8; j++)
            #pragma unroll
            for (int t = 0; t < 4; t++) c[i][j][t] = 0.f;

    auto load_stage = [&](int kt, int st) {
        int k0 = kt << 6;
        #pragma unroll
        for (int i = 0; i < 4; i++) {
            int cc = tid + 256 * i;          // 0..1023
            int row = cc >> 3, j = cc & 7;   // j: 8-half (16B) chunk
            cpasync16(asb + st * TILE_B + row * 144 + j * 16,
                      &A[(size_t)(bm0 + row) * K + k0 + j * 8]);
        }
        #pragma unroll
        for (int i = 0; i < 4; i++) {
            int cc = tid + 256 * i;
            int row = cc >> 3, j = cc & 7;
            cpasync16(bsb + st * TILE_B + row * 144 + j * 16,
                      &Bt[(size_t)(bn0 + row) * K + k0 + j * 8]);
        }
        cpcommit();
    };

    const int nk = K >> 6;
    load_stage(0, 0);

    int mi = lane >> 3, mr7 = lane & 7;
    for (int it = 0; it < nk; it++) {
        if (it + 1 < nk) { load_stage(it + 1, (it + 1) & 1); cpwait<1>(); }
        else cpwait<0>();
        __syncthreads();
        uint32_t ab = asb + (it & 1) * TILE_B;
        uint32_t bb = bsb + (it & 1) * TILE_B;
        #pragma unroll
        for (int ks = 0; ks < 4; ks++) {
            unsigned a[2][4], b[4][4];
            #pragma unroll
            for (int mt = 0; mt < 2; mt++) {
                int rowm = wm * 32 + mt * 16 + (mi & 1) * 8 + mr7;
                int col = ks * 16 + (mi >> 1) * 8;
                ldsm4(a[mt], ab + rowm * 144 + col * 2);
            }
            #pragma unroll
            for (int ntp = 0; ntp < 4; ntp++) {
                int rown = wn * 64 + ntp * 16 + (mi >> 1) * 8 + mr7;
                int col = ks * 16 + (mi & 1) * 8;
                ldsm4(b[ntp], bb + rown * 144 + col * 2);
            }
            #pragma unroll
            for (int mt = 0; mt < 2; mt++)
                #pragma unroll
                for (int ntp = 0; ntp < 4; ntp++) {
                    mma_f16(c[mt][2 * ntp + 0], a[mt], &b[ntp][0]);
                    mma_f16(c[mt][2 * ntp + 1], a[mt], &b[ntp][2]);
                }
        }
        __syncthreads();
    }

    // epilogue
    #pragma unroll
    for (int mt = 0; mt < 2; mt++) {
        #pragma unroll
        for (int nt = 0; nt < 8; nt++) {
            int r0 = bm0 + wm * 32 + mt * 16 + g;
            int cc = bn0 + wn * 64 + nt * 8 + 2 * q;
            float b0 = bias[cc], b1 = bias[cc + 1];
            #pragma unroll
            for (int half_ = 0; half_ < 2; half_++) {
                int r = r0 + half_ * 8;
                size_t o0 = (size_t)r * N + cc;
                float v0 = c[mt][nt][half_ * 2 + 0] + b0;
                float v1 = c[mt][nt][half_ * 2 + 1] + b1;
                if (EPI == EPI_GELU) { v0 = gelu_exact(v0); v1 = gelu_exact(v1); }
                else if (EPI == EPI_RES) {
                    v0 += resid[o0]; v1 += resid[o0 + 1];
                } else if (EPI == EPI_RESH) {
                    v0 = resid[o0] + 0.5f * v0; v1 = resid[o0 + 1] + 0.5f * v1;
                }
                if (OUTH) {
                    *(__half2*)((__half*)Cv + o0) = __floats2half2_rn(v0, v1);
                } else {
                    float* C = (float*)Cv;
                    C[o0] = v0; C[o0 + 1] = v1;
                }
            }
        }
    }
}

// ---------------- flash attention (tf32 mma internals, fp16 I/O) ----------------
// grid (T/128, B*NH), 256 threads. smem: QP[128*68], KsT[64*64], Vs[64*72] floats
__global__ __launch_bounds__(256) void attn2(const __half* __restrict__ qkv,
                                             __half* __restrict__ out) {
    extern __shared__ float sm[];
    float* QP  = sm;
    float* KsT = sm + 128 * 68;
    float* Vs  = KsT + 64 * 64;

    int bh = blockIdx.y;
    int b = bh >> 4, h = bh & 15;
    int qb = blockIdx.x;
    int tid = threadIdx.x, warp = tid >> 5, lane = tid & 31;
    int g = lane >> 2, q = lane & 3;
    int wrow = warp * 16;
    size_t base = (size_t)b * TT * 3072 + (size_t)h * 64;

    #pragma unroll
    for (int i = 0; i < 8; i++) {
        int cc = tid + 256 * i;
        int r = cc >> 4, c4 = (cc & 15) * 4;
        const __half2* p = (const __half2*)&qkv[base + (size_t)(qb * 128 + r) * 3072 + c4];
        float2 v0 = __half22float2(p[0]), v1 = __half22float2(p[1]);
        QP[r * 68 + c4 + 0] = v0.x * 0.125f;
        QP[r * 68 + c4 + 1] = v0.y * 0.125f;
        QP[r * 68 + c4 + 2] = v1.x * 0.125f;
        QP[r * 68 + c4 + 3] = v1.y * 0.125f;
    }
    __syncthreads();

    unsigned qa[8][4];
    #pragma unroll
    for (int s = 0; s < 8; s++) {
        qa[s][0] = fbits(QP[(wrow + g) * 68 + s * 8 + q]);
        qa[s][1] = fbits(QP[(wrow + g + 8) * 68 + s * 8 + q]);
        qa[s][2] = fbits(QP[(wrow + g) * 68 + s * 8 + q + 4]);
        qa[s][3] = fbits(QP[(wrow + g + 8) * 68 + s * 8 + q + 4]);
    }
    __syncthreads();

    float m0 = -1e30f, m1 = -1e30f, l0 = 0.f, l1 = 0.f;
    float o[8][4];
    #pragma unroll
    for (int nt = 0; nt < 8; nt++)
        #pragma unroll
        for (int t = 0; t < 4; t++) o[nt][t] = 0.f;

    int ktmax = 2 * qb + 1;
    for (int kt = 0; kt <= ktmax; kt++) {
        __syncthreads();
        #pragma unroll
        for (int i = 0; i < 4; i++) {
            int cc = tid + 256 * i;
            int r = cc >> 4, t = cc & 15, c4 = t * 4;
            const __half2* p = (const __half2*)&qkv[base + (size_t)(kt * 64 + r) * 3072 + 1024 + c4];
            float2 v0 = __half22float2(p[0]), v1 = __half22float2(p[1]);
            int sw = t << 1;
            KsT[(c4 + 0) * 64 + ((r ^ 0)  ^ sw)] = v0.x;
            KsT[(c4 + 1) * 64 + ((r ^ 8)  ^ sw)] = v0.y;
            KsT[(c4 + 2) * 64 + ((r ^ 16) ^ sw)] = v1.x;
            KsT[(c4 + 3) * 64 + ((r ^ 24) ^ sw)] = v1.y;
        }
        #pragma unroll
        for (int i = 0; i < 4; i++) {
            int cc = tid + 256 * i;
            int r = cc >> 4, c4 = (cc & 15) * 4;
            const __half2* p = (const __half2*)&qkv[base + (size_t)(kt * 64 + r) * 3072 + 2048 + c4];
            float2 v0 = __half22float2(p[0]), v1 = __half22float2(p[1]);
            Vs[r * 72 + c4 + 0] = v0.x;
            Vs[r * 72 + c4 + 1] = v0.y;
            Vs[r * 72 + c4 + 2] = v1.x;
            Vs[r * 72 + c4 + 3] = v1.y;
        }
        __syncthreads();

        bool active = (kt * 64) <= (qb * 128 + wrow + 15);
        if (active) {
            float s4[8][4];
            #pragma unroll
            for (int nt = 0; nt < 8; nt++)
                #pragma unroll
                for (int t = 0; t < 4; t++) s4[nt][t] = 0.f;
            #pragma unroll
            for (int s = 0; s < 8; s++) {
                int d0 = s * 8 + q, d1 = s * 8 + q + 4;
                int sw0 = ((d0 & 3) << 3) ^ ((d0 >> 2) << 1);
                int sw1 = ((d1 & 3) << 3) ^ ((d1 >> 2) << 1);
                unsigned kb[8][2];
                #pragma unroll
                for (int nt = 0; nt < 8; nt++) {
                    kb[nt][0] = fbits(KsT[d0 * 64 + ((nt * 8 + g) ^ sw0)]);
                    kb[nt][1] = fbits(KsT[d1 * 64 + ((nt * 8 + g) ^ sw1)]);
                }
                #pragma unroll
                for (int nt = 0; nt < 8; nt++) mma_tf32(s4[nt], qa[s], kb[nt]);
            }
            if (kt * 64 + 63 > qb * 128 + wrow) {
                int r0 = qb * 128 + wrow + g, r1 = r0 + 8;
                #pragma unroll
                for (int nt = 0; nt < 8; nt++) {
                    int c0 = kt * 64 + nt * 8 + 2 * q;
                    if (c0 > r0)     s4[nt][0] = -1e30f;
                    if (c0 + 1 > r0) s4[nt][1] = -1e30f;
                    if (c0 > r1)     s4[nt][2] = -1e30f;
                    if (c0 + 1 > r1) s4[nt][3] = -1e30f;
                }
            }
            float mx0 = -1e30f, mx1 = -1e30f;
            #pragma unroll
            for (int nt = 0; nt < 8; nt++) {
                mx0 = fmaxf(mx0, fmaxf(s4[nt][0], s4[nt][1]));
                mx1 = fmaxf(mx1, fmaxf(s4[nt][2], s4[nt][3]));
            }
            mx0 = fmaxf(mx0, __shfl_xor_sync(0xffffffffu, mx0, 1));
            mx0 = fmaxf(mx0, __shfl_xor_sync(0xffffffffu, mx0, 2));
            mx1 = fmaxf(mx1, __shfl_xor_sync(0xffffffffu, mx1, 1));
            mx1 = fmaxf(mx1, __shfl_xor_sync(0xffffffffu, mx1, 2));
            float mn0 = fmaxf(m0, mx0), mn1 = fmaxf(m1, mx1);
            float cr0 = exp2fast((m0 - mn0) * LOG2E);
            float cr1 = exp2fast((m1 - mn1) * LOG2E);
            float rs0 = 0.f, rs1 = 0.f;
            #pragma unroll
            for (int nt = 0; nt < 8; nt++) {
                float p0 = exp2fast((s4[nt][0] - mn0) * LOG2E);
                float p1 = exp2fast((s4[nt][1] - mn0) * LOG2E);
                float p2 = exp2fast((s4[nt][2] - mn1) * LOG2E);
                float p3 = exp2fast((s4[nt][3] - mn1) * LOG2E);
                rs0 += p0 + p1; rs1 += p2 + p3;
                float2 v01 = make_float2(tf32r(p0), tf32r(p1));
                *(float2*)&QP[(wrow + g) * 68 + nt * 8 + 2 * q] = v01;
                float2 v23 = make_float2(tf32r(p2), tf32r(p3));
                *(float2*)&QP[(wrow + g + 8) * 68 + nt * 8 + 2 * q] = v23;
            }
            rs0 += __shfl_xor_sync(0xffffffffu, rs0, 1);
            rs0 += __shfl_xor_sync(0xffffffffu, rs0, 2);
            rs1 += __shfl_xor_sync(0xffffffffu, rs1, 1);
            rs1 += __shfl_xor_sync(0xffffffffu, rs1, 2);
            l0 = l0 * cr0 + rs0; l1 = l1 * cr1 + rs1;
            #pragma unroll
            for (int nt = 0; nt < 8; nt++) {
                o[nt][0] *= cr0; o[nt][1] *= cr0;
                o[nt][2] *= cr1; o[nt][3] *= cr1;
            }
            m0 = mn0; m1 = mn1;
            __syncwarp();

            #pragma unroll
            for (int s = 0; s < 8; s++) {
                unsigned pa[4];
                pa[0] = fbits(QP[(wrow + g) * 68 + s * 8 + q]);
                pa[1] = fbits(QP[(wrow + g + 8) * 68 + s * 8 + q]);
                pa[2] = fbits(QP[(wrow + g) * 68 + s * 8 + q + 4]);
                pa[3] = fbits(QP[(wrow + g + 8) * 68 + s * 8 + q + 4]);
                unsigned vb[8][2];
                #pragma unroll
                for (int nt = 0; nt < 8; nt++) {
                    vb[nt][0] = fbits(Vs[(s * 8 + q) * 72 + nt * 8 + g]);
                    vb[nt][1] = fbits(Vs[(s * 8 + q + 4) * 72 + nt * 8 + g]);
                }
                #pragma unroll
                for (int nt = 0; nt < 8; nt++) mma_tf32(o[nt], pa, vb[nt]);
            }
        }
    }

    float i0 = 1.0f / l0, i1 = 1.0f / l1;
    int r0 = b * TT + qb * 128 + wrow + g;
    #pragma unroll
    for (int nt = 0; nt < 8; nt++) {
        int col = h * 64 + nt * 8 + 2 * q;
        *(__half2*)&out[(size_t)r0 * HH + col] = __floats2half2_rn(o[nt][0] * i0, o[nt][1] * i0);
        *(__half2*)&out[(size_t)(r0 + 8) * HH + col] = __floats2half2_rn(o[nt][2] * i1, o[nt][3] * i1);
    }
}

// ---------------- depthwise conv (K=3, causal) + gelu: fp16 in/out ----------------
__global__ void dwconv_gelu_kernel(const __half* __restrict__ ln, const float* __restrict__ dwk,
                                   const float* __restrict__ dwb, __half* __restrict__ out) {
    int i = blockIdx.x * blockDim.x + threadIdx.x;
    int ch = i & (HH - 1);
    int row = i >> 10;
    int t = row & (TT - 1);
    int b = row >> 10;
    float accv = dwb[ch];
    #pragma unroll
    for (int j = 0; j < 3; j++) {
        int tt = t - 2 + j;
        if (tt >= 0)
            accv += __half2float(ln[((size_t)(b * TT + tt)) * HH + ch]) * dwk[ch * 3 + j];
    }
    out[i] = __float2half_rn(gelu_exact(accv));
}

// ---------------- driver ----------------
extern "C" void kernel_launch(void* const* d_in, const int* in_sizes, int n_in,
                              void* d_out, int out_size) {
    const float* x       = (const float*)d_in[0];
    const float* ln1_g   = (const float*)d_in[1];
    const float* ln1_b   = (const float*)d_in[2];
    const float* ffn1_w1 = (const float*)d_in[3];
    const float* ffn1_b1 = (const float*)d_in[4];
    const float* ffn1_w2 = (const float*)d_in[5];
    const float* ffn1_b2 = (const float*)d_in[6];
    const float* an_g    = (const float*)d_in[7];
    const float* an_b    = (const float*)d_in[8];
    const float* qkv_w   = (const float*)d_in[9];
    const float* qkv_b   = (const float*)d_in[10];
    const float* out_w   = (const float*)d_in[11];
    const float* out_b   = (const float*)d_in[12];
    const float* cn_g    = (const float*)d_in[13];
    const float* cn_b    = (const float*)d_in[14];
    const float* dw_k    = (const float*)d_in[15];
    const float* dw_b    = (const float*)d_in[16];
    const float* pw_w    = (const float*)d_in[17];
    const float* pw_b    = (const float*)d_in[18];
    const float* ln2_g   = (const float*)d_in[19];
    const float* ln2_b   = (const float*)d_in[20];
    const float* ffn2_w1 = (const float*)d_in[21];
    const float* ffn2_b1 = (const float*)d_in[22];
    const float* ffn2_w2 = (const float*)d_in[23];
    const float* ffn2_b2 = (const float*)d_in[24];
    float* outp = (float*)d_out;

    float* p_x;
    __half *p_ln, *p_h, *p_qkv, *p_attn, *p_w;
    cudaGetSymbolAddress((void**)&p_x, g_x);
    cudaGetSymbolAddress((void**)&p_ln, g_lnh);
    cudaGetSymbolAddress((void**)&p_h, g_hh);
    cudaGetSymbolAddress((void**)&p_qkv, g_qkvh);
    cudaGetSymbolAddress((void**)&p_attn, g_attnh);
    cudaGetSymbolAddress((void**)&p_w, g_wh);

    const int smG = 4 * TILE_B;                             // 73728
    const int smAttn = (128 * 68 + 64 * 64 + 64 * 72) * 4;  // 69632
    cudaFuncSetAttribute(gemm4<EPI_BIAS, true>,  cudaFuncAttributeMaxDynamicSharedMemorySize, smG);
    cudaFuncSetAttribute(gemm4<EPI_GELU, true>,  cudaFuncAttributeMaxDynamicSharedMemorySize, smG);
    cudaFuncSetAttribute(gemm4<EPI_RES,  false>, cudaFuncAttributeMaxDynamicSharedMemorySize, smG);
    cudaFuncSetAttribute(gemm4<EPI_RESH, false>, cudaFuncAttributeMaxDynamicSharedMemorySize, smG);
    cudaFuncSetAttribute(attn2, cudaFuncAttributeMaxDynamicSharedMemorySize, smAttn);

    // weight prep: fp16 + transpose to [N,K] (pw_w already [N,K]: convert only)
    dim3 tb(32, 8);
    cvtT_kernel<<<dim3(1024 / 32, 2048 / 32), tb>>>(ffn1_w1, p_w + W_FFN1W1, 1024, 2048);
    cvtT_kernel<<<dim3(2048 / 32, 1024 / 32), tb>>>(ffn1_w2, p_w + W_FFN1W2, 2048, 1024);
    cvtT_kernel<<<dim3(1024 / 32, 3072 / 32), tb>>>(qkv_w,   p_w + W_QKVW,   1024, 3072);
    cvtT_kernel<<<dim3(1024 / 32, 1024 / 32), tb>>>(out_w,   p_w + W_OUTW,   1024, 1024);
    cvtw_kernel<<<(1048576 / 4) / 256, 256>>>((const float4*)pw_w, p_w + W_PWW, 1048576 / 4);
    cvtT_kernel<<<dim3(1024 / 32, 2048 / 32), tb>>>(ffn2_w1, p_w + W_FFN2W1, 1024, 2048);
    cvtT_kernel<<<dim3(2048 / 32, 1024 / 32), tb>>>(ffn2_w2, p_w + W_FFN2W2, 2048, 1024);

    dim3 blk(256);
    dim3 gN1024(1024 / 128, MROWS / 128);
    dim3 gN2048(2048 / 128, MROWS / 128);
    dim3 gN3072(3072 / 128, MROWS / 128);

    // 1) x = x + 0.5*FFN1(x)
    ln_kernel<<<MROWS, 256>>>(x, ln1_g, ln1_b, p_ln);
    gemm4<EPI_GELU, true><<<gN2048, blk, smG>>>(p_ln, p_w + W_FFN1W1, ffn1_b1, nullptr, p_h, 2048, 1024);
    gemm4<EPI_RESH, false><<<gN1024, blk, smG>>>(p_h, p_w + W_FFN1W2, ffn1_b2, x, p_x, 1024, 2048);

    // 2) attention
    ln_kernel<<<MROWS, 256>>>(p_x, an_g, an_b, p_ln);
    gemm4<EPI_BIAS, true><<<gN3072, blk, smG>>>(p_ln, p_w + W_QKVW, qkv_b, nullptr, p_qkv, 3072, 1024);
    attn2<<<dim3(TT / 128, BATCH * NHEAD), 256, smAttn>>>(p_qkv, p_attn);
    gemm4<EPI_RES, false><<<gN1024, blk, smG>>>(p_attn, p_w + W_OUTW, out_b, p_x, p_x, 1024, 1024);

    // 3) conv module
    ln_kernel<<<MROWS, 256>>>(p_x, cn_g, cn_b, p_ln);
    dwconv_gelu_kernel<<<(MROWS * HH) / 256, 256>>>(p_ln, dw_k, dw_b, p_h);
    gemm4<EPI_RES, false><<<gN1024, blk, smG>>>(p_h, p_w + W_PWW, pw_b, p_x, p_x, 1024, 1024);

    // 4) x = x + 0.5*FFN2(x)
    ln_kernel<<<MROWS, 256>>>(p_x, ln2_g, ln2_b, p_ln);
    gemm4<EPI_GELU, true><<<gN2048, blk, smG>>>(p_ln, p_w + W_FFN2W1, ffn2_b1, nullptr, p_h, 2048, 1024);
    gemm4<EPI_RESH, false><<<gN1024, blk, smG>>>(p_h, p_w + W_FFN2W2, ffn2_b2, p_x, outp, 1024, 2048);
}

// round 7
// speedup vs baseline: 3.8721x; 1.0992x over previous
#include <cuda_runtime.h>
#include <cuda_fp16.h>
#include <math.h>
#include <stdint.h>

// ---------------- problem constants ----------------
#define BATCH 8
#define TT 1024
#define HH 1024
#define NHEAD 16
#define MROWS (BATCH * TT)   // 8192

// ---------------- scratch (device globals) ----------------
__device__ float  g_x[MROWS * HH];            // residual stream (fp32)
__device__ __half g_lnh[MROWS * HH];          // LN output (fp16)
__device__ __half g_hh[MROWS * 2 * HH];       // FFN hidden / conv hidden (fp16)
__device__ __half g_qkvh[MROWS * 3 * HH];     // qkv (fp16)
__device__ __half g_attnh[MROWS * HH];        // attention out (fp16)
__device__ __half g_wh[13631488];             // fp16 TRANSPOSED weights [N,K]

#define W_FFN1W1 0
#define W_FFN1W2 2097152
#define W_QKVW   4194304
#define W_OUTW   7340032
#define W_PWW    8388608
#define W_FFN2W1 9437184
#define W_FFN2W2 11534336

// ---------------- helpers ----------------
__device__ __forceinline__ float gelu_exact(float x) { return x * normcdff(x); }
__device__ __forceinline__ unsigned h2u(__half2 h) { return *reinterpret_cast<unsigned*>(&h); }

__device__ __forceinline__ void mma_f16(float c[4], const unsigned a[4], const unsigned b[2]) {
    asm volatile(
        "mma.sync.aligned.m16n8k16.row.col.f32.f16.f16.f32 "
        "{%0,%1,%2,%3}, {%4,%5,%6,%7}, {%8,%9}, {%0,%1,%2,%3};"
        : "+f"(c[0]), "+f"(c[1]), "+f"(c[2]), "+f"(c[3])
        : "r"(a[0]), "r"(a[1]), "r"(a[2]), "r"(a[3]), "r"(b[0]), "r"(b[1]));
}

__device__ __forceinline__ void ldsm4(unsigned r[4], uint32_t a) {
    asm volatile("ldmatrix.sync.aligned.m8n8.x4.shared.b16 {%0,%1,%2,%3}, [%4];"
                 : "=r"(r[0]), "=r"(r[1]), "=r"(r[2]), "=r"(r[3]) : "r"(a));
}
__device__ __forceinline__ void ldsm4t(unsigned r[4], uint32_t a) {
    asm volatile("ldmatrix.sync.aligned.m8n8.x4.trans.shared.b16 {%0,%1,%2,%3}, [%4];"
                 : "=r"(r[0]), "=r"(r[1]), "=r"(r[2]), "=r"(r[3]) : "r"(a));
}

__device__ __forceinline__ void cpasync16(unsigned s, const void* g) {
    asm volatile("cp.async.cg.shared.global [%0], [%1], 16;\n" :: "r"(s), "l"(g));
}
__device__ __forceinline__ void cpcommit() { asm volatile("cp.async.commit_group;\n"); }
template <int N>
__device__ __forceinline__ void cpwait() { asm volatile("cp.async.wait_group %0;\n" :: "n"(N)); }

#define LOG2E 1.4426950408889634f
__device__ __forceinline__ float exp2fast(float t) {
    t = fmaxf(t, -126.0f);
    float fi = floorf(t);
    float f = t - fi;
    float p = 1.5403530e-4f;
    p = fmaf(p, f, 1.3333558e-3f);
    p = fmaf(p, f, 9.6180399e-3f);
    p = fmaf(p, f, 5.5504109e-2f);
    p = fmaf(p, f, 2.4022651e-1f);
    p = fmaf(p, f, 6.9314718e-1f);
    p = fmaf(p, f, 1.0f);
    float sc = __int_as_float(((int)fi + 127) << 23);
    return p * sc;
}

// ---------------- weight fp16 convert (pw_w: already [N,K]) ----------------
__global__ void cvtw_kernel(const float4* __restrict__ in, __half* __restrict__ out, int n4) {
    int i = blockIdx.x * blockDim.x + threadIdx.x;
    if (i < n4) {
        float4 v = in[i];
        __half2* o = (__half2*)(out + i * 4);
        o[0] = __floats2half2_rn(v.x, v.y);
        o[1] = __floats2half2_rn(v.z, v.w);
    }
}

// ---------------- weight fp16 convert + transpose: in[R,C] -> out[C,R] ----------------
__global__ void cvtT_kernel(const float* __restrict__ in, __half* __restrict__ out,
                            int R, int C) {
    __shared__ float t[32][33];
    int r0 = blockIdx.x * 32, c0 = blockIdx.y * 32;
    int tx = threadIdx.x, ty = threadIdx.y;  // 32 x 8
    #pragma unroll
    for (int i = 0; i < 4; i++)
        t[ty + i * 8][tx] = in[(size_t)(r0 + ty + i * 8) * C + c0 + tx];
    __syncthreads();
    #pragma unroll
    for (int i = 0; i < 4; i++)
        out[(size_t)(c0 + ty + i * 8) * R + r0 + tx] = __float2half_rn(t[tx][ty + i * 8]);
}

// ---------------- LayerNorm: fp32 in -> fp16 out ----------------
__global__ void ln_kernel(const float* __restrict__ in, const float* __restrict__ gam,
                          const float* __restrict__ bet, __half* __restrict__ out) {
    int row = blockIdx.x;
    int tid = threadIdx.x;  // 256
    const float4* p = (const float4*)(in + (size_t)row * HH);
    float4 v = p[tid];
    float s = v.x + v.y + v.z + v.w;
    float ss = v.x * v.x + v.y * v.y + v.z * v.z + v.w * v.w;
    #pragma unroll
    for (int o = 16; o > 0; o >>= 1) {
        s += __shfl_xor_sync(0xffffffffu, s, o);
        ss += __shfl_xor_sync(0xffffffffu, ss, o);
    }
    __shared__ float rs[8], rss[8];
    __shared__ float sh_mean, sh_rstd;
    if ((tid & 31) == 0) { rs[tid >> 5] = s; rss[tid >> 5] = ss; }
    __syncthreads();
    if (tid == 0) {
        float S = 0.f, SS = 0.f;
        #pragma unroll
        for (int i = 0; i < 8; i++) { S += rs[i]; SS += rss[i]; }
        float mean = S * (1.0f / HH);
        float var = SS * (1.0f / HH) - mean * mean;
        sh_mean = mean;
        sh_rstd = rsqrtf(var + 1e-5f);
    }
    __syncthreads();
    float mean = sh_mean, rstd = sh_rstd;
    float4 gv = ((const float4*)gam)[tid];
    float4 bv = ((const float4*)bet)[tid];
    __half2* o = (__half2*)(out + (size_t)row * HH + tid * 4);
    o[0] = __floats2half2_rn((v.x - mean) * rstd * gv.x + bv.x,
                             (v.y - mean) * rstd * gv.y + bv.y);
    o[1] = __floats2half2_rn((v.z - mean) * rstd * gv.z + bv.z,
                             (v.w - mean) * rstd * gv.w + bv.w);
}

// ---------------- FP16 tensor-core GEMM (unchanged from R6) ----------------
#define EPI_BIAS 0
#define EPI_GELU 1
#define EPI_RES  2
#define EPI_RESH 3

#define TILE_B (128 * 144)   // bytes per tile stage

template <int EPI, bool OUTH>
__global__ __launch_bounds__(256) void gemm4(
    const __half* __restrict__ A, const __half* __restrict__ Bt,
    const float* __restrict__ bias, const float* __restrict__ resid,
    void* __restrict__ Cv, int N, int K) {
    extern __shared__ char smc[];
    uint32_t asb = (uint32_t)__cvta_generic_to_shared(smc);
    uint32_t bsb = asb + 2 * TILE_B;

    int tid = threadIdx.x, warp = tid >> 5, lane = tid & 31;
    int wm = warp >> 1, wn = warp & 1, g = lane >> 2, q = lane & 3;
    int bm0 = blockIdx.y * 128, bn0 = blockIdx.x * 128;

    float c[2][8][4];
    #pragma unroll
    for (int i = 0; i < 2; i++)
        #pragma unroll
        for (int j = 0; j < 8; j++)
            #pragma unroll
            for (int t = 0; t < 4; t++) c[i][j][t] = 0.f;

    auto load_stage = [&](int kt, int st) {
        int k0 = kt << 6;
        #pragma unroll
        for (int i = 0; i < 4; i++) {
            int cc = tid + 256 * i;
            int row = cc >> 3, j = cc & 7;
            cpasync16(asb + st * TILE_B + row * 144 + j * 16,
                      &A[(size_t)(bm0 + row) * K + k0 + j * 8]);
        }
        #pragma unroll
        for (int i = 0; i < 4; i++) {
            int cc = tid + 256 * i;
            int row = cc >> 3, j = cc & 7;
            cpasync16(bsb + st * TILE_B + row * 144 + j * 16,
                      &Bt[(size_t)(bn0 + row) * K + k0 + j * 8]);
        }
        cpcommit();
    };

    const int nk = K >> 6;
    load_stage(0, 0);

    int mi = lane >> 3, mr7 = lane & 7;
    for (int it = 0; it < nk; it++) {
        if (it + 1 < nk) { load_stage(it + 1, (it + 1) & 1); cpwait<1>(); }
        else cpwait<0>();
        __syncthreads();
        uint32_t ab = asb + (it & 1) * TILE_B;
        uint32_t bb = bsb + (it & 1) * TILE_B;
        #pragma unroll
        for (int ks = 0; ks < 4; ks++) {
            unsigned a[2][4], b[4][4];
            #pragma unroll
            for (int mt = 0; mt < 2; mt++) {
                int rowm = wm * 32 + mt * 16 + (mi & 1) * 8 + mr7;
                int col = ks * 16 + (mi >> 1) * 8;
                ldsm4(a[mt], ab + rowm * 144 + col * 2);
            }
            #pragma unroll
            for (int ntp = 0; ntp < 4; ntp++) {
                int rown = wn * 64 + ntp * 16 + (mi >> 1) * 8 + mr7;
                int col = ks * 16 + (mi & 1) * 8;
                ldsm4(b[ntp], bb + rown * 144 + col * 2);
            }
            #pragma unroll
            for (int mt = 0; mt < 2; mt++)
                #pragma unroll
                for (int ntp = 0; ntp < 4; ntp++) {
                    mma_f16(c[mt][2 * ntp + 0], a[mt], &b[ntp][0]);
                    mma_f16(c[mt][2 * ntp + 1], a[mt], &b[ntp][2]);
                }
        }
        __syncthreads();
    }

    #pragma unroll
    for (int mt = 0; mt < 2; mt++) {
        #pragma unroll
        for (int nt = 0; nt < 8; nt++) {
            int r0 = bm0 + wm * 32 + mt * 16 + g;
            int cc = bn0 + wn * 64 + nt * 8 + 2 * q;
            float b0 = bias[cc], b1 = bias[cc + 1];
            #pragma unroll
            for (int half_ = 0; half_ < 2; half_++) {
                int r = r0 + half_ * 8;
                size_t o0 = (size_t)r * N + cc;
                float v0 = c[mt][nt][half_ * 2 + 0] + b0;
                float v1 = c[mt][nt][half_ * 2 + 1] + b1;
                if (EPI == EPI_GELU) { v0 = gelu_exact(v0); v1 = gelu_exact(v1); }
                else if (EPI == EPI_RES) {
                    v0 += resid[o0]; v1 += resid[o0 + 1];
                } else if (EPI == EPI_RESH) {
                    v0 = resid[o0] + 0.5f * v0; v1 = resid[o0 + 1] + 0.5f * v1;
                }
                if (OUTH) {
                    *(__half2*)((__half*)Cv + o0) = __floats2half2_rn(v0, v1);
                } else {
                    float* C = (float*)Cv;
                    C[o0] = v0; C[o0 + 1] = v1;
                }
            }
        }
    }
}

// ---------------- flash attention: full fp16 mma, P register-resident ----------------
// grid (T/128, B*NH), 256 threads (8 warps x 16 q-rows).
// smem (halves, stride 72): Qs[128][72], Ks[64][72], Vs[64][72] = 36864 B
__global__ __launch_bounds__(256) void attn3(const __half* __restrict__ qkv,
                                             __half* __restrict__ out) {
    extern __shared__ __half sh[];
    __half* Qs = sh;              // 128*72
    __half* Ks = sh + 128 * 72;   // 64*72
    __half* Vs = Ks + 64 * 72;    // 64*72
    uint32_t qsb = (uint32_t)__cvta_generic_to_shared(Qs);
    uint32_t ksb = (uint32_t)__cvta_generic_to_shared(Ks);
    uint32_t vsb = (uint32_t)__cvta_generic_to_shared(Vs);

    int bh = blockIdx.y;
    int b = bh >> 4, h = bh & 15;
    int qb = blockIdx.x;
    int tid = threadIdx.x, warp = tid >> 5, lane = tid & 31;
    int g = lane >> 2, q = lane & 3;
    int mi = lane >> 3, mr7 = lane & 7;
    int wrow = warp * 16;
    size_t base = (size_t)b * TT * 3072 + (size_t)h * 64;

    // load Q strip (scaled by 1/8, exact in fp16)
    {
        const __half2 sc2 = __floats2half2_rn(0.125f, 0.125f);
        #pragma unroll
        for (int i = 0; i < 4; i++) {
            int cc = tid + 256 * i;          // 1024 chunks of 8 halves
            int r = cc >> 3, j = cc & 7;
            uint4 v = *(const uint4*)&qkv[base + (size_t)(qb * 128 + r) * 3072 + j * 8];
            __half2* hv = (__half2*)&v;
            hv[0] = __hmul2(hv[0], sc2); hv[1] = __hmul2(hv[1], sc2);
            hv[2] = __hmul2(hv[2], sc2); hv[3] = __hmul2(hv[3], sc2);
            *(uint4*)&Qs[r * 72 + j * 8] = v;
        }
    }
    __syncthreads();

    // Q fragments (fp16 m16k16 x 4 along d)
    unsigned qa[4][4];
    #pragma unroll
    for (int kq = 0; kq < 4; kq++) {
        int rowm = wrow + (mi & 1) * 8 + mr7;
        int col = kq * 16 + (mi >> 1) * 8;
        ldsm4(qa[kq], qsb + (rowm * 72 + col) * 2);
    }

    float m0 = -1e30f, m1 = -1e30f, l0 = 0.f, l1 = 0.f;
    float o[8][4];
    #pragma unroll
    for (int nt = 0; nt < 8; nt++)
        #pragma unroll
        for (int t = 0; t < 4; t++) o[nt][t] = 0.f;

    int ktmax = 2 * qb + 1;
    for (int kt = 0; kt <= ktmax; kt++) {
        __syncthreads();  // protect Ks/Vs reuse
        #pragma unroll
        for (int i = 0; i < 2; i++) {
            int cc = tid + 256 * i;          // 512 chunks
            int r = cc >> 3, j = cc & 7;
            uint4 v = *(const uint4*)&qkv[base + (size_t)(kt * 64 + r) * 3072 + 1024 + j * 8];
            *(uint4*)&Ks[r * 72 + j * 8] = v;
            uint4 w = *(const uint4*)&qkv[base + (size_t)(kt * 64 + r) * 3072 + 2048 + j * 8];
            *(uint4*)&Vs[r * 72 + j * 8] = w;
        }
        __syncthreads();

        bool active = (kt * 64) <= (qb * 128 + wrow + 15);
        if (active) {
            // S = Q @ K^T  (K natural [t][d] layout is the B operand)
            float s4[8][4];
            #pragma unroll
            for (int nt = 0; nt < 8; nt++)
                #pragma unroll
                for (int t = 0; t < 4; t++) s4[nt][t] = 0.f;
            #pragma unroll
            for (int kq = 0; kq < 4; kq++) {
                #pragma unroll
                for (int ntp = 0; ntp < 4; ntp++) {
                    unsigned kb[4];
                    int rown = ntp * 16 + (mi >> 1) * 8 + mr7;
                    int col = kq * 16 + (mi & 1) * 8;
                    ldsm4(kb, ksb + (rown * 72 + col) * 2);
                    mma_f16(s4[2 * ntp + 0], qa[kq], &kb[0]);
                    mma_f16(s4[2 * ntp + 1], qa[kq], &kb[2]);
                }
            }
            // causal mask
            if (kt * 64 + 63 > qb * 128 + wrow) {
                int r0 = qb * 128 + wrow + g, r1 = r0 + 8;
                #pragma unroll
                for (int nt = 0; nt < 8; nt++) {
                    int c0 = kt * 64 + nt * 8 + 2 * q;
                    if (c0 > r0)     s4[nt][0] = -1e30f;
                    if (c0 + 1 > r0) s4[nt][1] = -1e30f;
                    if (c0 > r1)     s4[nt][2] = -1e30f;
                    if (c0 + 1 > r1) s4[nt][3] = -1e30f;
                }
            }
            // online softmax (rows g, g+8); stats over 4 q-lanes
            float mx0 = -1e30f, mx1 = -1e30f;
            #pragma unroll
            for (int nt = 0; nt < 8; nt++) {
                mx0 = fmaxf(mx0, fmaxf(s4[nt][0], s4[nt][1]));
                mx1 = fmaxf(mx1, fmaxf(s4[nt][2], s4[nt][3]));
            }
            mx0 = fmaxf(mx0, __shfl_xor_sync(0xffffffffu, mx0, 1));
            mx0 = fmaxf(mx0, __shfl_xor_sync(0xffffffffu, mx0, 2));
            mx1 = fmaxf(mx1, __shfl_xor_sync(0xffffffffu, mx1, 1));
            mx1 = fmaxf(mx1, __shfl_xor_sync(0xffffffffu, mx1, 2));
            float mn0 = fmaxf(m0, mx0), mn1 = fmaxf(m1, mx1);
            float cr0 = exp2fast((m0 - mn0) * LOG2E);
            float cr1 = exp2fast((m1 - mn1) * LOG2E);
            float rs0 = 0.f, rs1 = 0.f;
            unsigned plo[8], phi[8];
            #pragma unroll
            for (int nt = 0; nt < 8; nt++) {
                float p0 = exp2fast((s4[nt][0] - mn0) * LOG2E);
                float p1 = exp2fast((s4[nt][1] - mn0) * LOG2E);
                float p2 = exp2fast((s4[nt][2] - mn1) * LOG2E);
                float p3 = exp2fast((s4[nt][3] - mn1) * LOG2E);
                rs0 += p0 + p1; rs1 += p2 + p3;
                __half2 hlo = __floats2half2_rn(p0, p1);
                __half2 hhi = __floats2half2_rn(p2, p3);
                plo[nt] = h2u(hlo); phi[nt] = h2u(hhi);
            }
            rs0 += __shfl_xor_sync(0xffffffffu, rs0, 1);
            rs0 += __shfl_xor_sync(0xffffffffu, rs0, 2);
            rs1 += __shfl_xor_sync(0xffffffffu, rs1, 1);
            rs1 += __shfl_xor_sync(0xffffffffu, rs1, 2);
            l0 = l0 * cr0 + rs0; l1 = l1 * cr1 + rs1;
            #pragma unroll
            for (int nt = 0; nt < 8; nt++) {
                o[nt][0] *= cr0; o[nt][1] *= cr0;
                o[nt][2] *= cr1; o[nt][3] *= cr1;
            }
            m0 = mn0; m1 = mn1;

            // O += P @ V  (P register-resident; V^T via ldmatrix.trans)
            #pragma unroll
            for (int ks = 0; ks < 4; ks++) {
                unsigned pa[4] = {plo[2 * ks], phi[2 * ks], plo[2 * ks + 1], phi[2 * ks + 1]};
                #pragma unroll
                for (int ntp = 0; ntp < 4; ntp++) {
                    unsigned vb[4];
                    int rowt = ks * 16 + (mi & 1) * 8 + mr7;
                    int cold = ntp * 16 + (mi >> 1) * 8;
                    ldsm4t(vb, vsb + (rowt * 72 + cold) * 2);
                    mma_f16(o[2 * ntp + 0], pa, &vb[0]);
                    mma_f16(o[2 * ntp + 1], pa, &vb[2]);
                }
            }
        }
    }

    // epilogue: normalize, store fp16
    float i0 = 1.0f / l0, i1 = 1.0f / l1;
    int r0 = b * TT + qb * 128 + wrow + g;
    #pragma unroll
    for (int nt = 0; nt < 8; nt++) {
        int col = h * 64 + nt * 8 + 2 * q;
        *(__half2*)&out[(size_t)r0 * HH + col] = __floats2half2_rn(o[nt][0] * i0, o[nt][1] * i0);
        *(__half2*)&out[(size_t)(r0 + 8) * HH + col] = __floats2half2_rn(o[nt][2] * i1, o[nt][3] * i1);
    }
}

// ---------------- depthwise conv (K=3, causal) + gelu: fp16 in/out ----------------
__global__ void dwconv_gelu_kernel(const __half* __restrict__ ln, const float* __restrict__ dwk,
                                   const float* __restrict__ dwb, __half* __restrict__ out) {
    int i = blockIdx.x * blockDim.x + threadIdx.x;
    int ch = i & (HH - 1);
    int row = i >> 10;
    int t = row & (TT - 1);
    int b = row >> 10;
    float accv = dwb[ch];
    #pragma unroll
    for (int j = 0; j < 3; j++) {
        int tt = t - 2 + j;
        if (tt >= 0)
            accv += __half2float(ln[((size_t)(b * TT + tt)) * HH + ch]) * dwk[ch * 3 + j];
    }
    out[i] = __float2half_rn(gelu_exact(accv));
}

// ---------------- driver ----------------
extern "C" void kernel_launch(void* const* d_in, const int* in_sizes, int n_in,
                              void* d_out, int out_size) {
    const float* x       = (const float*)d_in[0];
    const float* ln1_g   = (const float*)d_in[1];
    const float* ln1_b   = (const float*)d_in[2];
    const float* ffn1_w1 = (const float*)d_in[3];
    const float* ffn1_b1 = (const float*)d_in[4];
    const float* ffn1_w2 = (const float*)d_in[5];
    const float* ffn1_b2 = (const float*)d_in[6];
    const float* an_g    = (const float*)d_in[7];
    const float* an_b    = (const float*)d_in[8];
    const float* qkv_w   = (const float*)d_in[9];
    const float* qkv_b   = (const float*)d_in[10];
    const float* out_w   = (const float*)d_in[11];
    const float* out_b   = (const float*)d_in[12];
    const float* cn_g    = (const float*)d_in[13];
    const float* cn_b    = (const float*)d_in[14];
    const float* dw_k    = (const float*)d_in[15];
    const float* dw_b    = (const float*)d_in[16];
    const float* pw_w    = (const float*)d_in[17];
    const float* pw_b    = (const float*)d_in[18];
    const float* ln2_g   = (const float*)d_in[19];
    const float* ln2_b   = (const float*)d_in[20];
    const float* ffn2_w1 = (const float*)d_in[21];
    const float* ffn2_b1 = (const float*)d_in[22];
    const float* ffn2_w2 = (const float*)d_in[23];
    const float* ffn2_b2 = (const float*)d_in[24];
    float* outp = (float*)d_out;

    float* p_x;
    __half *p_ln, *p_h, *p_qkv, *p_attn, *p_w;
    cudaGetSymbolAddress((void**)&p_x, g_x);
    cudaGetSymbolAddress((void**)&p_ln, g_lnh);
    cudaGetSymbolAddress((void**)&p_h, g_hh);
    cudaGetSymbolAddress((void**)&p_qkv, g_qkvh);
    cudaGetSymbolAddress((void**)&p_attn, g_attnh);
    cudaGetSymbolAddress((void**)&p_w, g_wh);

    const int smG = 4 * TILE_B;                 // 73728
    const int smAttn = (128 + 64 + 64) * 72 * 2;  // 36864
    cudaFuncSetAttribute(gemm4<EPI_BIAS, true>,  cudaFuncAttributeMaxDynamicSharedMemorySize, smG);
    cudaFuncSetAttribute(gemm4<EPI_GELU, true>,  cudaFuncAttributeMaxDynamicSharedMemorySize, smG);
    cudaFuncSetAttribute(gemm4<EPI_RES,  false>, cudaFuncAttributeMaxDynamicSharedMemorySize, smG);
    cudaFuncSetAttribute(gemm4<EPI_RESH, false>, cudaFuncAttributeMaxDynamicSharedMemorySize, smG);
    cudaFuncSetAttribute(attn3, cudaFuncAttributeMaxDynamicSharedMemorySize, smAttn);

    // weight prep: fp16 + transpose to [N,K] (pw_w already [N,K]: convert only)
    dim3 tb(32, 8);
    cvtT_kernel<<<dim3(1024 / 32, 2048 / 32), tb>>>(ffn1_w1, p_w + W_FFN1W1, 1024, 2048);
    cvtT_kernel<<<dim3(2048 / 32, 1024 / 32), tb>>>(ffn1_w2, p_w + W_FFN1W2, 2048, 1024);
    cvtT_kernel<<<dim3(1024 / 32, 3072 / 32), tb>>>(qkv_w,   p_w + W_QKVW,   1024, 3072);
    cvtT_kernel<<<dim3(1024 / 32, 1024 / 32), tb>>>(out_w,   p_w + W_OUTW,   1024, 1024);
    cvtw_kernel<<<(1048576 / 4) / 256, 256>>>((const float4*)pw_w, p_w + W_PWW, 1048576 / 4);
    cvtT_kernel<<<dim3(1024 / 32, 2048 / 32), tb>>>(ffn2_w1, p_w + W_FFN2W1, 1024, 2048);
    cvtT_kernel<<<dim3(2048 / 32, 1024 / 32), tb>>>(ffn2_w2, p_w + W_FFN2W2, 2048, 1024);

    dim3 blk(256);
    dim3 gN1024(1024 / 128, MROWS / 128);
    dim3 gN2048(2048 / 128, MROWS / 128);
    dim3 gN3072(3072 / 128, MROWS / 128);

    // 1) x = x + 0.5*FFN1(x)
    ln_kernel<<<MROWS, 256>>>(x, ln1_g, ln1_b, p_ln);
    gemm4<EPI_GELU, true><<<gN2048, blk, smG>>>(p_ln, p_w + W_FFN1W1, ffn1_b1, nullptr, p_h, 2048, 1024);
    gemm4<EPI_RESH, false><<<gN1024, blk, smG>>>(p_h, p_w + W_FFN1W2, ffn1_b2, x, p_x, 1024, 2048);

    // 2) attention
    ln_kernel<<<MROWS, 256>>>(p_x, an_g, an_b, p_ln);
    gemm4<EPI_BIAS, true><<<gN3072, blk, smG>>>(p_ln, p_w + W_QKVW, qkv_b, nullptr, p_qkv, 3072, 1024);
    attn3<<<dim3(TT / 128, BATCH * NHEAD), 256, smAttn>>>(p_qkv, p_attn);
    gemm4<EPI_RES, false><<<gN1024, blk, smG>>>(p_attn, p_w + W_OUTW, out_b, p_x, p_x, 1024, 1024);

    // 3) conv module
    ln_kernel<<<MROWS, 256>>>(p_x, cn_g, cn_b, p_ln);
    dwconv_gelu_kernel<<<(MROWS * HH) / 256, 256>>>(p_ln, dw_k, dw_b, p_h);
    gemm4<EPI_RES, false><<<gN1024, blk, smG>>>(p_h, p_w + W_PWW, pw_b, p_x, p_x, 1024, 1024);

    // 4) x = x + 0.5*FFN2(x)
    ln_kernel<<<MROWS, 256>>>(p_x, ln2_g, ln2_b, p_ln);
    gemm4<EPI_GELU, true><<<gN2048, blk, smG>>>(p_ln, p_w + W_FFN2W1, ffn2_b1, nullptr, p_h, 2048, 1024);
    gemm4<EPI_RESH, false><<<gN1024, blk, smG>>>(p_h, p_w + W_FFN2W2, ffn2_b2, p_x, outp, 1024, 2048);
}

// round 8
// speedup vs baseline: 4.0433x; 1.0442x over previous
#include <cuda_runtime.h>
#include <cuda_fp16.h>
#include <math.h>
#include <stdint.h>

// ---------------- problem constants ----------------
#define BATCH 8
#define TT 1024
#define HH 1024
#define NHEAD 16
#define MROWS (BATCH * TT)   // 8192

// ---------------- scratch (device globals) ----------------
__device__ float  g_x[MROWS * HH];            // residual stream (fp32)
__device__ __half g_lnh[MROWS * HH];          // LN output (fp16)
__device__ __half g_hh[MROWS * 2 * HH];       // FFN hidden / conv hidden (fp16)
__device__ __half g_qkvh[MROWS * 3 * HH];     // qkv (fp16)
__device__ __half g_attnh[MROWS * HH];        // attention out (fp16)
__device__ __half g_wh[13631488];             // fp16 TRANSPOSED weights [N,K]

#define W_FFN1W1 0
#define W_FFN1W2 2097152
#define W_QKVW   4194304
#define W_OUTW   7340032
#define W_PWW    8388608
#define W_FFN2W1 9437184
#define W_FFN2W2 11534336

// ---------------- helpers ----------------
__device__ __forceinline__ float gelu_exact(float x) { return x * normcdff(x); }
__device__ __forceinline__ unsigned h2u(__half2 h) { return *reinterpret_cast<unsigned*>(&h); }

__device__ __forceinline__ void mma_f16(float c[4], const unsigned a[4], const unsigned b[2]) {
    asm volatile(
        "mma.sync.aligned.m16n8k16.row.col.f32.f16.f16.f32 "
        "{%0,%1,%2,%3}, {%4,%5,%6,%7}, {%8,%9}, {%0,%1,%2,%3};"
        : "+f"(c[0]), "+f"(c[1]), "+f"(c[2]), "+f"(c[3])
        : "r"(a[0]), "r"(a[1]), "r"(a[2]), "r"(a[3]), "r"(b[0]), "r"(b[1]));
}

__device__ __forceinline__ void ldsm4(unsigned r[4], uint32_t a) {
    asm volatile("ldmatrix.sync.aligned.m8n8.x4.shared.b16 {%0,%1,%2,%3}, [%4];"
                 : "=r"(r[0]), "=r"(r[1]), "=r"(r[2]), "=r"(r[3]) : "r"(a));
}
__device__ __forceinline__ void ldsm4t(unsigned r[4], uint32_t a) {
    asm volatile("ldmatrix.sync.aligned.m8n8.x4.trans.shared.b16 {%0,%1,%2,%3}, [%4];"
                 : "=r"(r[0]), "=r"(r[1]), "=r"(r[2]), "=r"(r[3]) : "r"(a));
}

__device__ __forceinline__ void cpasync16(unsigned s, const void* g) {
    asm volatile("cp.async.cg.shared.global [%0], [%1], 16;\n" :: "r"(s), "l"(g));
}
__device__ __forceinline__ void cpcommit() { asm volatile("cp.async.commit_group;\n"); }
template <int N>
__device__ __forceinline__ void cpwait() { asm volatile("cp.async.wait_group %0;\n" :: "n"(N)); }

#define LOG2E 1.4426950408889634f
__device__ __forceinline__ float exp2fast(float t) {
    t = fmaxf(t, -126.0f);
    float fi = floorf(t);
    float f = t - fi;
    float p = 1.5403530e-4f;
    p = fmaf(p, f, 1.3333558e-3f);
    p = fmaf(p, f, 9.6180399e-3f);
    p = fmaf(p, f, 5.5504109e-2f);
    p = fmaf(p, f, 2.4022651e-1f);
    p = fmaf(p, f, 6.9314718e-1f);
    p = fmaf(p, f, 1.0f);
    float sc = __int_as_float(((int)fi + 127) << 23);
    return p * sc;
}

// ---------------- weight fp16 convert (pw_w: already [N,K]) ----------------
__global__ void cvtw_kernel(const float4* __restrict__ in, __half* __restrict__ out, int n4) {
    int i = blockIdx.x * blockDim.x + threadIdx.x;
    if (i < n4) {
        float4 v = in[i];
        __half2* o = (__half2*)(out + i * 4);
        o[0] = __floats2half2_rn(v.x, v.y);
        o[1] = __floats2half2_rn(v.z, v.w);
    }
}

// ---------------- weight fp16 convert + transpose: in[R,C] -> out[C,R] ----------------
__global__ void cvtT_kernel(const float* __restrict__ in, __half* __restrict__ out,
                            int R, int C) {
    __shared__ float t[32][33];
    int r0 = blockIdx.x * 32, c0 = blockIdx.y * 32;
    int tx = threadIdx.x, ty = threadIdx.y;  // 32 x 8
    #pragma unroll
    for (int i = 0; i < 4; i++)
        t[ty + i * 8][tx] = in[(size_t)(r0 + ty + i * 8) * C + c0 + tx];
    __syncthreads();
    #pragma unroll
    for (int i = 0; i < 4; i++)
        out[(size_t)(c0 + ty + i * 8) * R + r0 + tx] = __float2half_rn(t[tx][ty + i * 8]);
}

// ---------------- LayerNorm: fp32 in -> fp16 out ----------------
__global__ void ln_kernel(const float* __restrict__ in, const float* __restrict__ gam,
                          const float* __restrict__ bet, __half* __restrict__ out) {
    int row = blockIdx.x;
    int tid = threadIdx.x;  // 256
    const float4* p = (const float4*)(in + (size_t)row * HH);
    float4 v = p[tid];
    float s = v.x + v.y + v.z + v.w;
    float ss = v.x * v.x + v.y * v.y + v.z * v.z + v.w * v.w;
    #pragma unroll
    for (int o = 16; o > 0; o >>= 1) {
        s += __shfl_xor_sync(0xffffffffu, s, o);
        ss += __shfl_xor_sync(0xffffffffu, ss, o);
    }
    __shared__ float rs[8], rss[8];
    __shared__ float sh_mean, sh_rstd;
    if ((tid & 31) == 0) { rs[tid >> 5] = s; rss[tid >> 5] = ss; }
    __syncthreads();
    if (tid == 0) {
        float S = 0.f, SS = 0.f;
        #pragma unroll
        for (int i = 0; i < 8; i++) { S += rs[i]; SS += rss[i]; }
        float mean = S * (1.0f / HH);
        float var = SS * (1.0f / HH) - mean * mean;
        sh_mean = mean;
        sh_rstd = rsqrtf(var + 1e-5f);
    }
    __syncthreads();
    float mean = sh_mean, rstd = sh_rstd;
    float4 gv = ((const float4*)gam)[tid];
    float4 bv = ((const float4*)bet)[tid];
    __half2* o = (__half2*)(out + (size_t)row * HH + tid * 4);
    o[0] = __floats2half2_rn((v.x - mean) * rstd * gv.x + bv.x,
                             (v.y - mean) * rstd * gv.y + bv.y);
    o[1] = __floats2half2_rn((v.z - mean) * rstd * gv.z + bv.z,
                             (v.w - mean) * rstd * gv.w + bv.w);
}

// ---------------- FP16 tensor-core GEMM ----------------
#define EPI_BIAS 0
#define EPI_GELU 1
#define EPI_RES  2
#define EPI_RESH 3

#define TILE_B (128 * 144)   // bytes per tile stage

template <int EPI, bool OUTH>
__global__ __launch_bounds__(256, 2) void gemm4(
    const __half* __restrict__ A, const __half* __restrict__ Bt,
    const float* __restrict__ bias, const float* __restrict__ resid,
    void* __restrict__ Cv, int N, int K) {
    extern __shared__ char smc[];
    uint32_t asb = (uint32_t)__cvta_generic_to_shared(smc);
    uint32_t bsb = asb + 2 * TILE_B;

    int tid = threadIdx.x, warp = tid >> 5, lane = tid & 31;
    int wm = warp >> 1, wn = warp & 1, g = lane >> 2, q = lane & 3;
    int bm0 = blockIdx.y * 128, bn0 = blockIdx.x * 128;

    float c[2][8][4];
    #pragma unroll
    for (int i = 0; i < 2; i++)
        #pragma unroll
        for (int j = 0; j < 8; j++)
            #pragma unroll
            for (int t = 0; t < 4; t++) c[i][j][t] = 0.f;

    auto load_stage = [&](int kt, int st) {
        int k0 = kt << 6;
        #pragma unroll
        for (int i = 0; i < 4; i++) {
            int cc = tid + 256 * i;
            int row = cc >> 3, j = cc & 7;
            cpasync16(asb + st * TILE_B + row * 144 + j * 16,
                      &A[(size_t)(bm0 + row) * K + k0 + j * 8]);
        }
        #pragma unroll
        for (int i = 0; i < 4; i++) {
            int cc = tid + 256 * i;
            int row = cc >> 3, j = cc & 7;
            cpasync16(bsb + st * TILE_B + row * 144 + j * 16,
                      &Bt[(size_t)(bn0 + row) * K + k0 + j * 8]);
        }
        cpcommit();
    };

    const int nk = K >> 6;
    load_stage(0, 0);

    int mi = lane >> 3, mr7 = lane & 7;
    for (int it = 0; it < nk; it++) {
        if (it + 1 < nk) { load_stage(it + 1, (it + 1) & 1); cpwait<1>(); }
        else cpwait<0>();
        __syncthreads();
        uint32_t ab = asb + (it & 1) * TILE_B;
        uint32_t bb = bsb + (it & 1) * TILE_B;
        #pragma unroll
        for (int ks = 0; ks < 4; ks++) {
            unsigned a[2][4], b[4][4];
            #pragma unroll
            for (int mt = 0; mt < 2; mt++) {
                int rowm = wm * 32 + mt * 16 + (mi & 1) * 8 + mr7;
                int col = ks * 16 + (mi >> 1) * 8;
                ldsm4(a[mt], ab + rowm * 144 + col * 2);
            }
            #pragma unroll
            for (int ntp = 0; ntp < 4; ntp++) {
                int rown = wn * 64 + ntp * 16 + (mi >> 1) * 8 + mr7;
                int col = ks * 16 + (mi & 1) * 8;
                ldsm4(b[ntp], bb + rown * 144 + col * 2);
            }
            #pragma unroll
            for (int mt = 0; mt < 2; mt++)
                #pragma unroll
                for (int ntp = 0; ntp < 4; ntp++) {
                    mma_f16(c[mt][2 * ntp + 0], a[mt], &b[ntp][0]);
                    mma_f16(c[mt][2 * ntp + 1], a[mt], &b[ntp][2]);
                }
        }
        __syncthreads();
    }

    #pragma unroll
    for (int mt = 0; mt < 2; mt++) {
        #pragma unroll
        for (int nt = 0; nt < 8; nt++) {
            int r0 = bm0 + wm * 32 + mt * 16 + g;
            int cc = bn0 + wn * 64 + nt * 8 + 2 * q;
            float b0 = bias[cc], b1 = bias[cc + 1];
            #pragma unroll
            for (int half_ = 0; half_ < 2; half_++) {
                int r = r0 + half_ * 8;
                size_t o0 = (size_t)r * N + cc;
                float v0 = c[mt][nt][half_ * 2 + 0] + b0;
                float v1 = c[mt][nt][half_ * 2 + 1] + b1;
                if (EPI == EPI_GELU) { v0 = gelu_exact(v0); v1 = gelu_exact(v1); }
                else if (EPI == EPI_RES) {
                    v0 += resid[o0]; v1 += resid[o0 + 1];
                } else if (EPI == EPI_RESH) {
                    v0 = resid[o0] + 0.5f * v0; v1 = resid[o0 + 1] + 0.5f * v1;
                }
                if (OUTH) {
                    *(__half2*)((__half*)Cv + o0) = __floats2half2_rn(v0, v1);
                } else {
                    float* C = (float*)Cv;
                    C[o0] = v0; C[o0 + 1] = v1;
                }
            }
        }
    }
}

// ---------------- flash attention: fp16 mma, cp.async double-buffered K/V ----------------
// grid (T/128, B*NH), 256 threads (8 warps x 16 q-rows).
// smem (halves, stride 72): Qs[128][72], Ks[2][64][72], Vs[2][64][72] = 55296 B
#define KV_STG (64 * 72)     // halves per K or V stage

__global__ __launch_bounds__(256) void attn4(const __half* __restrict__ qkv,
                                             __half* __restrict__ out) {
    extern __shared__ __half sh[];
    uint32_t qsb = (uint32_t)__cvta_generic_to_shared(sh);
    uint32_t ksb = qsb + 128 * 72 * 2;
    uint32_t vsb = ksb + 2 * KV_STG * 2;

    int bh = blockIdx.y;
    int b = bh >> 4, h = bh & 15;
    int qb = blockIdx.x;
    int tid = threadIdx.x, warp = tid >> 5, lane = tid & 31;
    int g = lane >> 2, q = lane & 3;
    int mi = lane >> 3, mr7 = lane & 7;
    int wrow = warp * 16;
    size_t base = (size_t)b * TT * 3072 + (size_t)h * 64;

    auto load_kv = [&](int kt, int st) {
        size_t rowb = base + (size_t)(kt * 64) * 3072;
        #pragma unroll
        for (int i = 0; i < 2; i++) {
            int cc = tid + 256 * i;          // 0..511
            int r = cc >> 3, j = cc & 7;
            size_t go = rowb + (size_t)r * 3072 + j * 8;
            cpasync16(ksb + (st * KV_STG + r * 72 + j * 8) * 2, &qkv[go + 1024]);
            cpasync16(vsb + (st * KV_STG + r * 72 + j * 8) * 2, &qkv[go + 2048]);
        }
        cpcommit();
    };

    // Q prefetch (unscaled; scale folded into S)
    #pragma unroll
    for (int i = 0; i < 4; i++) {
        int cc = tid + 256 * i;
        int r = cc >> 3, j = cc & 7;
        cpasync16(qsb + (r * 72 + j * 8) * 2,
                  &qkv[base + (size_t)(qb * 128 + r) * 3072 + j * 8]);
    }
    cpcommit();
    load_kv(0, 0);
    cpwait<0>();
    __syncthreads();

    // Q fragments
    unsigned qa[4][4];
    #pragma unroll
    for (int kq = 0; kq < 4; kq++) {
        int rowm = wrow + (mi & 1) * 8 + mr7;
        int col = kq * 16 + (mi >> 1) * 8;
        ldsm4(qa[kq], qsb + (rowm * 72 + col) * 2);
    }

    float m0 = -1e30f, m1 = -1e30f, l0 = 0.f, l1 = 0.f;
    float o[8][4];
    #pragma unroll
    for (int nt = 0; nt < 8; nt++)
        #pragma unroll
        for (int t = 0; t < 4; t++) o[nt][t] = 0.f;

    int ktmax = 2 * qb + 1;
    for (int kt = 0; kt <= ktmax; kt++) {
        int st = kt & 1;
        if (kt < ktmax) { load_kv(kt + 1, st ^ 1); cpwait<1>(); }
        else cpwait<0>();
        __syncthreads();

        bool active = (kt * 64) <= (qb * 128 + wrow + 15);
        if (active) {
            uint32_t kb0 = ksb + st * KV_STG * 2;
            uint32_t vb0 = vsb + st * KV_STG * 2;
            // S = Q @ K^T
            float s4[8][4];
            #pragma unroll
            for (int nt = 0; nt < 8; nt++)
                #pragma unroll
                for (int t = 0; t < 4; t++) s4[nt][t] = 0.f;
            #pragma unroll
            for (int kq = 0; kq < 4; kq++) {
                #pragma unroll
                for (int ntp = 0; ntp < 4; ntp++) {
                    unsigned kb[4];
                    int rown = ntp * 16 + (mi >> 1) * 8 + mr7;
                    int col = kq * 16 + (mi & 1) * 8;
                    ldsm4(kb, kb0 + (rown * 72 + col) * 2);
                    mma_f16(s4[2 * ntp + 0], qa[kq], &kb[0]);
                    mma_f16(s4[2 * ntp + 1], qa[kq], &kb[2]);
                }
            }
            // scale 1/sqrt(64)
            #pragma unroll
            for (int nt = 0; nt < 8; nt++)
                #pragma unroll
                for (int t = 0; t < 4; t++) s4[nt][t] *= 0.125f;
            // causal mask
            if (kt * 64 + 63 > qb * 128 + wrow) {
                int r0 = qb * 128 + wrow + g, r1 = r0 + 8;
                #pragma unroll
                for (int nt = 0; nt < 8; nt++) {
                    int c0 = kt * 64 + nt * 8 + 2 * q;
                    if (c0 > r0)     s4[nt][0] = -1e30f;
                    if (c0 + 1 > r0) s4[nt][1] = -1e30f;
                    if (c0 > r1)     s4[nt][2] = -1e30f;
                    if (c0 + 1 > r1) s4[nt][3] = -1e30f;
                }
            }
            // online softmax
            float mx0 = -1e30f, mx1 = -1e30f;
            #pragma unroll
            for (int nt = 0; nt < 8; nt++) {
                mx0 = fmaxf(mx0, fmaxf(s4[nt][0], s4[nt][1]));
                mx1 = fmaxf(mx1, fmaxf(s4[nt][2], s4[nt][3]));
            }
            mx0 = fmaxf(mx0, __shfl_xor_sync(0xffffffffu, mx0, 1));
            mx0 = fmaxf(mx0, __shfl_xor_sync(0xffffffffu, mx0, 2));
            mx1 = fmaxf(mx1, __shfl_xor_sync(0xffffffffu, mx1, 1));
            mx1 = fmaxf(mx1, __shfl_xor_sync(0xffffffffu, mx1, 2));
            float mn0 = fmaxf(m0, mx0), mn1 = fmaxf(m1, mx1);
            float cr0 = exp2fast((m0 - mn0) * LOG2E);
            float cr1 = exp2fast((m1 - mn1) * LOG2E);
            float rs0 = 0.f, rs1 = 0.f;
            unsigned plo[8], phi[8];
            #pragma unroll
            for (int nt = 0; nt < 8; nt++) {
                float p0 = exp2fast((s4[nt][0] - mn0) * LOG2E);
                float p1 = exp2fast((s4[nt][1] - mn0) * LOG2E);
                float p2 = exp2fast((s4[nt][2] - mn1) * LOG2E);
                float p3 = exp2fast((s4[nt][3] - mn1) * LOG2E);
                rs0 += p0 + p1; rs1 += p2 + p3;
                plo[nt] = h2u(__floats2half2_rn(p0, p1));
                phi[nt] = h2u(__floats2half2_rn(p2, p3));
            }
            rs0 += __shfl_xor_sync(0xffffffffu, rs0, 1);
            rs0 += __shfl_xor_sync(0xffffffffu, rs0, 2);
            rs1 += __shfl_xor_sync(0xffffffffu, rs1, 1);
            rs1 += __shfl_xor_sync(0xffffffffu, rs1, 2);
            l0 = l0 * cr0 + rs0; l1 = l1 * cr1 + rs1;
            #pragma unroll
            for (int nt = 0; nt < 8; nt++) {
                o[nt][0] *= cr0; o[nt][1] *= cr0;
                o[nt][2] *= cr1; o[nt][3] *= cr1;
            }
            m0 = mn0; m1 = mn1;

            // O += P @ V (P register-resident; V^T via ldmatrix.trans)
            #pragma unroll
            for (int ks = 0; ks < 4; ks++) {
                unsigned pa[4] = {plo[2 * ks], phi[2 * ks], plo[2 * ks + 1], phi[2 * ks + 1]};
                #pragma unroll
                for (int ntp = 0; ntp < 4; ntp++) {
                    unsigned vb[4];
                    int rowt = ks * 16 + (mi & 1) * 8 + mr7;
                    int cold = ntp * 16 + (mi >> 1) * 8;
                    ldsm4t(vb, vb0 + (rowt * 72 + cold) * 2);
                    mma_f16(o[2 * ntp + 0], pa, &vb[0]);
                    mma_f16(o[2 * ntp + 1], pa, &vb[2]);
                }
            }
        }
        __syncthreads();
    }

    // epilogue: normalize, store fp16
    float i0 = 1.0f / l0, i1 = 1.0f / l1;
    int r0 = b * TT + qb * 128 + wrow + g;
    #pragma unroll
    for (int nt = 0; nt < 8; nt++) {
        int col = h * 64 + nt * 8 + 2 * q;
        *(__half2*)&out[(size_t)r0 * HH + col] = __floats2half2_rn(o[nt][0] * i0, o[nt][1] * i0);
        *(__half2*)&out[(size_t)(r0 + 8) * HH + col] = __floats2half2_rn(o[nt][2] * i1, o[nt][3] * i1);
    }
}

// ---------------- depthwise conv (K=3, causal) + gelu: vectorized 8ch/thread ----------------
__global__ void dwconv_gelu_kernel(const __half* __restrict__ ln, const float* __restrict__ dwk,
                                   const float* __restrict__ dwb, __half* __restrict__ out) {
    int idx = blockIdx.x * blockDim.x + threadIdx.x;   // MROWS*HH/8 threads
    int ch0 = (idx & 127) * 8;
    int row = idx >> 7;
    int t = row & (TT - 1);
    size_t rb = (size_t)row * HH + ch0;
    uint4 v0 = make_uint4(0, 0, 0, 0), v1 = make_uint4(0, 0, 0, 0);
    uint4 v2 = *(const uint4*)&ln[rb];
    if (t >= 2) v0 = *(const uint4*)&ln[rb - 2 * HH];
    if (t >= 1) v1 = *(const uint4*)&ln[rb - HH];
    const __half* h0 = (const __half*)&v0;
    const __half* h1 = (const __half*)&v1;
    const __half* h2 = (const __half*)&v2;
    __half outv[8];
    #pragma unroll
    for (int c = 0; c < 8; c++) {
        int ch = ch0 + c;
        float acc = dwb[ch]
            + __half2float(h0[c]) * dwk[ch * 3 + 0]
            + __half2float(h1[c]) * dwk[ch * 3 + 1]
            + __half2float(h2[c]) * dwk[ch * 3 + 2];
        outv[c] = __float2half_rn(gelu_exact(acc));
    }
    *(uint4*)&out[rb] = *(uint4*)outv;
}

// ---------------- driver ----------------
extern "C" void kernel_launch(void* const* d_in, const int* in_sizes, int n_in,
                              void* d_out, int out_size) {
    const float* x       = (const float*)d_in[0];
    const float* ln1_g   = (const float*)d_in[1];
    const float* ln1_b   = (const float*)d_in[2];
    const float* ffn1_w1 = (const float*)d_in[3];
    const float* ffn1_b1 = (const float*)d_in[4];
    const float* ffn1_w2 = (const float*)d_in[5];
    const float* ffn1_b2 = (const float*)d_in[6];
    const float* an_g    = (const float*)d_in[7];
    const float* an_b    = (const float*)d_in[8];
    const float* qkv_w   = (const float*)d_in[9];
    const float* qkv_b   = (const float*)d_in[10];
    const float* out_w   = (const float*)d_in[11];
    const float* out_b   = (const float*)d_in[12];
    const float* cn_g    = (const float*)d_in[13];
    const float* cn_b    = (const float*)d_in[14];
    const float* dw_k    = (const float*)d_in[15];
    const float* dw_b    = (const float*)d_in[16];
    const float* pw_w    = (const float*)d_in[17];
    const float* pw_b    = (const float*)d_in[18];
    const float* ln2_g   = (const float*)d_in[19];
    const float* ln2_b   = (const float*)d_in[20];
    const float* ffn2_w1 = (const float*)d_in[21];
    const float* ffn2_b1 = (const float*)d_in[22];
    const float* ffn2_w2 = (const float*)d_in[23];
    const float* ffn2_b2 = (const float*)d_in[24];
    float* outp = (float*)d_out;

    float* p_x;
    __half *p_ln, *p_h, *p_qkv, *p_attn, *p_w;
    cudaGetSymbolAddress((void**)&p_x, g_x);
    cudaGetSymbolAddress((void**)&p_ln, g_lnh);
    cudaGetSymbolAddress((void**)&p_h, g_hh);
    cudaGetSymbolAddress((void**)&p_qkv, g_qkvh);
    cudaGetSymbolAddress((void**)&p_attn, g_attnh);
    cudaGetSymbolAddress((void**)&p_w, g_wh);

    const int smG = 4 * TILE_B;                       // 73728
    const int smAttn = (128 + 4 * 64) * 72 * 2;       // 55296
    cudaFuncSetAttribute(gemm4<EPI_BIAS, true>,  cudaFuncAttributeMaxDynamicSharedMemorySize, smG);
    cudaFuncSetAttribute(gemm4<EPI_GELU, true>,  cudaFuncAttributeMaxDynamicSharedMemorySize, smG);
    cudaFuncSetAttribute(gemm4<EPI_RES,  false>, cudaFuncAttributeMaxDynamicSharedMemorySize, smG);
    cudaFuncSetAttribute(gemm4<EPI_RESH, false>, cudaFuncAttributeMaxDynamicSharedMemorySize, smG);
    cudaFuncSetAttribute(attn4, cudaFuncAttributeMaxDynamicSharedMemorySize, smAttn);

    // weight prep: fp16 + transpose to [N,K] (pw_w already [N,K]: convert only)
    dim3 tb(32, 8);
    cvtT_kernel<<<dim3(1024 / 32, 2048 / 32), tb>>>(ffn1_w1, p_w + W_FFN1W1, 1024, 2048);
    cvtT_kernel<<<dim3(2048 / 32, 1024 / 32), tb>>>(ffn1_w2, p_w + W_FFN1W2, 2048, 1024);
    cvtT_kernel<<<dim3(1024 / 32, 3072 / 32), tb>>>(qkv_w,   p_w + W_QKVW,   1024, 3072);
    cvtT_kernel<<<dim3(1024 / 32, 1024 / 32), tb>>>(out_w,   p_w + W_OUTW,   1024, 1024);
    cvtw_kernel<<<(1048576 / 4) / 256, 256>>>((const float4*)pw_w, p_w + W_PWW, 1048576 / 4);
    cvtT_kernel<<<dim3(1024 / 32, 2048 / 32), tb>>>(ffn2_w1, p_w + W_FFN2W1, 1024, 2048);
    cvtT_kernel<<<dim3(2048 / 32, 1024 / 32), tb>>>(ffn2_w2, p_w + W_FFN2W2, 2048, 1024);

    dim3 blk(256);
    dim3 gN1024(1024 / 128, MROWS / 128);
    dim3 gN2048(2048 / 128, MROWS / 128);
    dim3 gN3072(3072 / 128, MROWS / 128);

    // 1) x = x + 0.5*FFN1(x)
    ln_kernel<<<MROWS, 256>>>(x, ln1_g, ln1_b, p_ln);
    gemm4<EPI_GELU, true><<<gN2048, blk, smG>>>(p_ln, p_w + W_FFN1W1, ffn1_b1, nullptr, p_h, 2048, 1024);
    gemm4<EPI_RESH, false><<<gN1024, blk, smG>>>(p_h, p_w + W_FFN1W2, ffn1_b2, x, p_x, 1024, 2048);

    // 2) attention
    ln_kernel<<<MROWS, 256>>>(p_x, an_g, an_b, p_ln);
    gemm4<EPI_BIAS, true><<<gN3072, blk, smG>>>(p_ln, p_w + W_QKVW, qkv_b, nullptr, p_qkv, 3072, 1024);
    attn4<<<dim3(TT / 128, BATCH * NHEAD), 256, smAttn>>>(p_qkv, p_attn);
    gemm4<EPI_RES, false><<<gN1024, blk, smG>>>(p_attn, p_w + W_OUTW, out_b, p_x, p_x, 1024, 1024);

    // 3) conv module
    ln_kernel<<<MROWS, 256>>>(p_x, cn_g, cn_b, p_ln);
    dwconv_gelu_kernel<<<(MROWS * HH / 8) / 256, 256>>>(p_ln, dw_k, dw_b, p_h);
    gemm4<EPI_RES, false><<<gN1024, blk, smG>>>(p_h, p_w + W_PWW, pw_b, p_x, p_x, 1024, 1024);

    // 4) x = x + 0.5*FFN2(x)
    ln_kernel<<<MROWS, 256>>>(p_x, ln2_g, ln2_b, p_ln);
    gemm4<EPI_GELU, true><<<gN2048, blk, smG>>>(p_ln, p_w + W_FFN2W1, ffn2_b1, nullptr, p_h, 2048, 1024);
    gemm4<EPI_RESH, false><<<gN1024, blk, smG>>>(p_h, p_w + W_FFN2W2, ffn2_b2, p_x, outp, 1024, 2048);
}